// round 10
// baseline (speedup 1.0000x reference)
#include <cuda_runtime.h>
#include <cstdint>
#include <math.h>

#define B_ROWS 16384
#define K_DIM  1024
#define H_DIM  1024
#define FH     4096
#define EPS    1e-5f

// Scratch: [i2h 64M][h2h 64M][xc 16M][hc 16M][Wic 4M][Whc 4M][stats 64K][cnt 128]
#define OFF_I2H   0
#define OFF_H2H   67108864ull
#define OFF_XC    134217728ull
#define OFF_HC    150994944ull
#define OFF_WIC   167772160ull
#define OFF_WHC   171966464ull
#define OFF_STATS 176160768ull
#define OFF_CNT   176226304ull
__device__ float g_scratch[176226432];

__device__ __forceinline__ uint32_t smem_u32(const void* p) {
    uint32_t a;
    asm("{ .reg .u64 t; cvta.to.shared.u64 t, %1; cvt.u32.u64 %0, t; }" : "=r"(a) : "l"(p));
    return a;
}

// ===========================================================================
// tf32 RN conversion pass
// ===========================================================================
__global__ void conv_tf32_kernel(const float4* __restrict__ in, uint4* __restrict__ out, int n4) {
    for (int i = blockIdx.x * blockDim.x + threadIdx.x; i < n4; i += gridDim.x * blockDim.x) {
        float4 v = in[i];
        uint4 o;
        asm("cvt.rna.tf32.f32 %0, %1;" : "=r"(o.x) : "f"(v.x));
        asm("cvt.rna.tf32.f32 %0, %1;" : "=r"(o.y) : "f"(v.y));
        asm("cvt.rna.tf32.f32 %0, %1;" : "=r"(o.z) : "f"(v.z));
        asm("cvt.rna.tf32.f32 %0, %1;" : "=r"(o.w) : "f"(v.w));
        out[i] = o;
    }
}

// Zero the LN stats buffer (65536 floats) + completion counters (128 ints)
__global__ void zero_stats_kernel() {
    const int idx = blockIdx.x * 256 + threadIdx.x;
    if (idx < 16416) {
        float4* p = (float4*)(g_scratch + OFF_STATS);
        p[idx] = make_float4(0.f, 0.f, 0.f, 0.f);
    }
}

// ===========================================================================
// tf32 mma.sync GEMM, tile 128(M) x 256(N) x 32(K), 256 threads,
// 8 warps (2m x 4n), warp tile 64x64, 4-stage cp.async ring, fused LN stats,
// + completion-counter LSTM finisher (last CTA of each m-block).
// ===========================================================================
#define STAGES 4
#define ITERS  32
#define STAGE_BYTES 49152     // A 16KB + B 32KB
#define ROW_BYTES 128

__device__ __forceinline__ void stage_load(uint32_t abase, uint32_t bbase,
                                           const float* __restrict__ A, const float* __restrict__ W,
                                           int m0, int n0, int kb, int tid) {
    #pragma unroll
    for (int i = 0; i < 4; i++) {
        int c = tid + i * 256;
        int r = c >> 3, q = c & 7;
        uint32_t sw = (uint32_t)(r * ROW_BYTES + ((q ^ (r & 7)) << 4));
        const float* ga = A + (size_t)(m0 + r) * K_DIM + kb + q * 4;
        asm volatile("cp.async.cg.shared.global [%0], [%1], 16;" :: "r"(abase + sw), "l"(ga));
    }
    #pragma unroll
    for (int i = 0; i < 8; i++) {
        int c = tid + i * 256;
        int r = c >> 3, q = c & 7;
        uint32_t sw = (uint32_t)(r * ROW_BYTES + ((q ^ (r & 7)) << 4));
        const float* gb = W + (size_t)(n0 + r) * K_DIM + kb + q * 4;
        asm volatile("cp.async.cg.shared.global [%0], [%1], 16;" :: "r"(bbase + sw), "l"(gb));
    }
    asm volatile("cp.async.commit_group;" ::: "memory");
}

#define LDSM_X4(r0, r1, r2, r3, a) \
    asm volatile("ldmatrix.sync.aligned.m8n8.x4.shared.b16 {%0,%1,%2,%3}, [%4];" \
        : "=r"(r0), "=r"(r1), "=r"(r2), "=r"(r3) : "r"(a))

#define MMA_TF32(d, a, b) \
    asm volatile("mma.sync.aligned.m16n8k8.row.col.f32.tf32.tf32.f32 " \
        "{%0,%1,%2,%3}, {%4,%5,%6,%7}, {%8,%9}, {%0,%1,%2,%3};" \
        : "+f"((d)[0]), "+f"((d)[1]), "+f"((d)[2]), "+f"((d)[3]) \
        : "r"((a)[0]), "r"((a)[1]), "r"((a)[2]), "r"((a)[3]), "r"((b)[0]), "r"((b)[1]))

__device__ __forceinline__ float sigf(float x) { return 1.f / (1.f + expf(-x)); }

__global__ void __launch_bounds__(256, 1) gemm_tc_kernel(
    const float* __restrict__ A0, const float* __restrict__ A1,
    const float* __restrict__ W0, const float* __restrict__ W1,
    const float* __restrict__ c,
    const float* __restrict__ gi, const float* __restrict__ bi,
    const float* __restrict__ gh, const float* __restrict__ bh,
    const float* __restrict__ gc, const float* __restrict__ bc,
    const float* __restrict__ bias,
    float* __restrict__ out)
{
    extern __shared__ __align__(128) char smem[];
    __shared__ int last_flag;
    const uint32_t sb = smem_u32(smem);
    const int tid = threadIdx.x, wid = tid >> 5, l = tid & 31;
    const int n0 = blockIdx.x * 256;
    const int z = blockIdx.y;
    const int m0 = blockIdx.z * 128;
    const float* A = z ? A1 : A0;
    const float* W = z ? W1 : W0;
    float* C = g_scratch + (z ? OFF_H2H : OFF_I2H);
    float* stats = g_scratch + OFF_STATS + (size_t)z * B_ROWS * 2;

    const int mw = (wid & 1) * 64;
    const int nw = (wid >> 1) * 64;

    const int rA0 = mw + ((l >> 3) & 1) * 8 + (l & 7);
    const int cbA = (l >> 4);
    const int rB0 = nw + (l >> 4) * 8 + (l & 7);
    const int cbB = (l >> 3) & 1;

    uint32_t offA[4]; int xA[4];
    #pragma unroll
    for (int mf = 0; mf < 4; mf++) { int r = rA0 + mf * 16; offA[mf] = r * ROW_BYTES; xA[mf] = r & 7; }
    uint32_t offB[4]; int xB[4];
    #pragma unroll
    for (int p = 0; p < 4; p++) { int r = rB0 + p * 16; offB[p] = r * ROW_BYTES; xB[p] = r & 7; }

    float acc[4][8][4];
    #pragma unroll
    for (int mf = 0; mf < 4; mf++)
        #pragma unroll
        for (int nf = 0; nf < 8; nf++)
            #pragma unroll
            for (int e = 0; e < 4; e++) acc[mf][nf][e] = 0.f;

    #pragma unroll
    for (int s = 0; s < STAGES - 1; s++)
        stage_load(sb + s * STAGE_BYTES, sb + s * STAGE_BYTES + 16384, A, W, m0, n0, s * 32, tid);

    uint32_t af[2][4][4];
    uint32_t bf[2][4][4];

    for (int kt = 0; kt < ITERS; kt++) {
        asm volatile("cp.async.wait_group 2;" ::: "memory");
        __syncthreads();
        const uint32_t Ab = sb + (kt & (STAGES - 1)) * STAGE_BYTES;
        const uint32_t Bb = Ab + 16384;

        #pragma unroll
        for (int mf = 0; mf < 4; mf++) {
            uint32_t a = Ab + offA[mf] + ((cbA ^ xA[mf]) << 4);
            LDSM_X4(af[0][mf][0], af[0][mf][1], af[0][mf][2], af[0][mf][3], a);
        }
        #pragma unroll
        for (int p = 0; p < 4; p++) {
            uint32_t a = Bb + offB[p] + ((cbB ^ xB[p]) << 4);
            LDSM_X4(bf[0][p][0], bf[0][p][1], bf[0][p][2], bf[0][p][3], a);
        }

        if (kt + STAGES - 1 < ITERS) {
            const uint32_t Pb = sb + ((kt + STAGES - 1) & (STAGES - 1)) * STAGE_BYTES;
            stage_load(Pb, Pb + 16384, A, W, m0, n0, (kt + STAGES - 1) * 32, tid);
        } else {
            asm volatile("cp.async.commit_group;" ::: "memory");
        }

        #pragma unroll
        for (int j = 0; j < 4; j++) {
            const int cur = j & 1, nxt = cur ^ 1;
            if (j < 3) {
                const int q = 2 * (j + 1);
                #pragma unroll
                for (int mf = 0; mf < 4; mf++) {
                    uint32_t a = Ab + offA[mf] + (((q + cbA) ^ xA[mf]) << 4);
                    LDSM_X4(af[nxt][mf][0], af[nxt][mf][1], af[nxt][mf][2], af[nxt][mf][3], a);
                }
                #pragma unroll
                for (int p = 0; p < 4; p++) {
                    uint32_t a = Bb + offB[p] + (((q + cbB) ^ xB[p]) << 4);
                    LDSM_X4(bf[nxt][p][0], bf[nxt][p][1], bf[nxt][p][2], bf[nxt][p][3], a);
                }
            }
            #pragma unroll
            for (int mf = 0; mf < 4; mf++)
                #pragma unroll
                for (int nf = 0; nf < 8; nf++) {
                    uint32_t b2[2] = { bf[cur][nf >> 1][(nf & 1) * 2], bf[cur][nf >> 1][(nf & 1) * 2 + 1] };
                    MMA_TF32(acc[mf][nf], af[cur][mf], b2);
                }
        }
    }

    // ---- store C + fused per-row LN partial stats ----
    const int g = l >> 2, cc = (l & 3) * 2;
    #pragma unroll
    for (int mf = 0; mf < 4; mf++) {
        float s0 = 0.f, q0 = 0.f, s1 = 0.f, q1 = 0.f;
        #pragma unroll
        for (int nf = 0; nf < 8; nf++) {
            const int col = n0 + nw + nf * 8 + cc;
            float* p0 = C + (size_t)(m0 + mw + mf * 16 + g) * FH + col;
            float* p1 = p0 + 8 * FH;
            asm volatile("st.global.v2.f32 [%0], {%1,%2};" :: "l"(p0), "f"(acc[mf][nf][0]), "f"(acc[mf][nf][1]) : "memory");
            asm volatile("st.global.v2.f32 [%0], {%1,%2};" :: "l"(p1), "f"(acc[mf][nf][2]), "f"(acc[mf][nf][3]) : "memory");
            s0 += acc[mf][nf][0] + acc[mf][nf][1];
            q0 += acc[mf][nf][0] * acc[mf][nf][0] + acc[mf][nf][1] * acc[mf][nf][1];
            s1 += acc[mf][nf][2] + acc[mf][nf][3];
            q1 += acc[mf][nf][2] * acc[mf][nf][2] + acc[mf][nf][3] * acc[mf][nf][3];
        }
        #pragma unroll
        for (int o = 1; o < 4; o <<= 1) {
            s0 += __shfl_xor_sync(0xffffffffu, s0, o);
            q0 += __shfl_xor_sync(0xffffffffu, q0, o);
            s1 += __shfl_xor_sync(0xffffffffu, s1, o);
            q1 += __shfl_xor_sync(0xffffffffu, q1, o);
        }
        if ((l & 3) == 0) {
            const int r0 = m0 + mw + mf * 16 + g;
            atomicAdd(&stats[(size_t)r0 * 2 + 0], s0);
            atomicAdd(&stats[(size_t)r0 * 2 + 1], q0);
            atomicAdd(&stats[(size_t)(r0 + 8) * 2 + 0], s1);
            atomicAdd(&stats[(size_t)(r0 + 8) * 2 + 1], q1);
        }
    }

    // ---- completion counter: last of 32 CTAs (16 n x 2 z) runs LSTM finisher ----
    __threadfence();
    __syncthreads();
    if (tid == 0) {
        int* cnt = (int*)(g_scratch + OFF_CNT);
        last_flag = (atomicAdd(&cnt[blockIdx.z], 1) == 31) ? 1 : 0;
    }
    __syncthreads();
    if (!last_flag) return;
    __threadfence();

    // ---- LSTM finisher: 128 rows, one warp per row (shfl-only reductions) ----
    {
        const float inv = 1.f / (float)FH;
        const float invH = 1.f / (float)H_DIM;
        const float2* stp = (const float2*)(g_scratch + OFF_STATS);
        const float* i2hB = g_scratch + OFF_I2H;
        const float* h2hB = g_scratch + OFF_H2H;
        float* out_h = out;
        float* out_c = out + (size_t)B_ROWS * H_DIM;

        for (int rr = wid; rr < 128; rr += 8) {
            const int row = m0 + rr;
            const float2 sti = stp[row];
            const float2 sth = stp[B_ROWS + row];
            const float mu_i = sti.x * inv, mu_h = sth.x * inv;
            const float rs_i = rsqrtf(sti.y * inv - mu_i * mu_i + EPS);
            const float rs_h = rsqrtf(sth.y * inv - mu_h * mu_h + EPS);
            const float* pi = i2hB + (size_t)row * FH;
            const float* ph = h2hB + (size_t)row * FH;

            float4 cnA[8], loA[8];
            float cs1 = 0.f, cs2 = 0.f;
            #pragma unroll
            for (int j = 0; j < 8; j++) {
                const int col = j * 128 + l * 4;
                float4 r[4];
                #pragma unroll
                for (int gg2 = 0; gg2 < 4; gg2++) {
                    const int jo = gg2 * 1024 + col;
                    const float4 vi = *(const float4*)(pi + jo);
                    const float4 vh = *(const float4*)(ph + jo);
                    const float4 ga = *(const float4*)(gi + jo);
                    const float4 ba = *(const float4*)(bi + jo);
                    const float4 gb2 = *(const float4*)(gh + jo);
                    const float4 bb = *(const float4*)(bh + jo);
                    const float4 bs = *(const float4*)(bias + jo);
                    r[gg2].x = (vi.x - mu_i) * rs_i * ga.x + ba.x + (vh.x - mu_h) * rs_h * gb2.x + bb.x + bs.x;
                    r[gg2].y = (vi.y - mu_i) * rs_i * ga.y + ba.y + (vh.y - mu_h) * rs_h * gb2.y + bb.y + bs.y;
                    r[gg2].z = (vi.z - mu_i) * rs_i * ga.z + ba.z + (vh.z - mu_h) * rs_h * gb2.z + bb.z + bs.z;
                    r[gg2].w = (vi.w - mu_i) * rs_i * ga.w + ba.w + (vh.w - mu_h) * rs_h * gb2.w + bb.w + bs.w;
                }
                const float4 co = *(const float4*)(c + (size_t)row * H_DIM + col);
                float4 cn;
                cn.x = sigf(r[0].x) * co.x + sigf(r[1].x) * tanhf(r[3].x);
                cn.y = sigf(r[0].y) * co.y + sigf(r[1].y) * tanhf(r[3].y);
                cn.z = sigf(r[0].z) * co.z + sigf(r[1].z) * tanhf(r[3].z);
                cn.w = sigf(r[0].w) * co.w + sigf(r[1].w) * tanhf(r[3].w);
                cnA[j] = cn; loA[j] = r[2];
                *(float4*)(out_c + (size_t)row * H_DIM + col) = cn;
                cs1 += cn.x + cn.y + cn.z + cn.w;
                cs2 += cn.x * cn.x + cn.y * cn.y + cn.z * cn.z + cn.w * cn.w;
            }
            #pragma unroll
            for (int o = 16; o > 0; o >>= 1) {
                cs1 += __shfl_xor_sync(0xffffffffu, cs1, o);
                cs2 += __shfl_xor_sync(0xffffffffu, cs2, o);
            }
            const float mu_c = cs1 * invH;
            const float rs_c = rsqrtf(cs2 * invH - mu_c * mu_c + EPS);
            #pragma unroll
            for (int j = 0; j < 8; j++) {
                const int col = j * 128 + l * 4;
                const float4 gcv = *(const float4*)(gc + col);
                const float4 bcv = *(const float4*)(bc + col);
                float4 hv;
                hv.x = sigf(loA[j].x) * tanhf((cnA[j].x - mu_c) * rs_c * gcv.x + bcv.x);
                hv.y = sigf(loA[j].y) * tanhf((cnA[j].y - mu_c) * rs_c * gcv.y + bcv.y);
                hv.z = sigf(loA[j].z) * tanhf((cnA[j].z - mu_c) * rs_c * gcv.z + bcv.z);
                hv.w = sigf(loA[j].w) * tanhf((cnA[j].w - mu_c) * rs_c * gcv.w + bcv.w);
                *(float4*)(out_h + (size_t)row * H_DIM + col) = hv;
            }
        }
    }
}

// ===========================================================================
extern "C" void kernel_launch(void* const* d_in, const int* in_sizes, int n_in,
                              void* d_out, int out_size) {
    const float* x    = (const float*)d_in[0];
    const float* h    = (const float*)d_in[1];
    const float* c    = (const float*)d_in[2];
    const float* Wi   = (const float*)d_in[3];
    const float* Wh   = (const float*)d_in[4];
    const float* gi   = (const float*)d_in[5];
    const float* bi   = (const float*)d_in[6];
    const float* gh   = (const float*)d_in[7];
    const float* bh   = (const float*)d_in[8];
    const float* gc   = (const float*)d_in[9];
    const float* bc   = (const float*)d_in[10];
    const float* bias = (const float*)d_in[11];
    float* out = (float*)d_out;

    float* base = nullptr;
    cudaGetSymbolAddress((void**)&base, g_scratch);
    cudaFuncSetAttribute(gemm_tc_kernel, cudaFuncAttributeMaxDynamicSharedMemorySize,
                         STAGES * STAGE_BYTES);
    float* xc  = base + OFF_XC;
    float* hc  = base + OFF_HC;
    float* Wic = base + OFF_WIC;
    float* Whc = base + OFF_WHC;

    // 1) zero stats + counters
    zero_stats_kernel<<<65, 256>>>();

    // 2) RN-convert operands to tf32
    conv_tf32_kernel<<<4096, 256>>>((const float4*)x,  (uint4*)xc,  (B_ROWS * K_DIM) / 4);
    conv_tf32_kernel<<<4096, 256>>>((const float4*)h,  (uint4*)hc,  (B_ROWS * H_DIM) / 4);
    conv_tf32_kernel<<<2048, 256>>>((const float4*)Wi, (uint4*)Wic, (FH * K_DIM) / 4);
    conv_tf32_kernel<<<2048, 256>>>((const float4*)Wh, (uint4*)Whc, (FH * H_DIM) / 4);

    // 3) tensor-core GEMMs + fused LN stats + counter-gated LSTM finisher
    dim3 gg(FH / 256, 2, B_ROWS / 128);
    gemm_tc_kernel<<<gg, 256, STAGES * STAGE_BYTES>>>(xc, hc, Wic, Whc,
                                                      c, gi, bi, gh, bh, gc, bc, bias, out);
}

// round 11
// speedup vs baseline: 1.3027x; 1.3027x over previous
#include <cuda_runtime.h>
#include <cstdint>
#include <math.h>

#define B_ROWS 16384
#define K_DIM  1024
#define H_DIM  1024
#define FH     4096
#define EPS    1e-5f

// Scratch: [i2h 64M][h2h 64M][xc 16M][hc 16M][Wic 4M][Whc 4M][stats 64K] floats
#define OFF_I2H   0
#define OFF_H2H   67108864ull
#define OFF_XC    134217728ull
#define OFF_HC    150994944ull
#define OFF_WIC   167772160ull
#define OFF_WHC   171966464ull
#define OFF_STATS 176160768ull
__device__ float g_scratch[176226304];

__device__ __forceinline__ uint32_t smem_u32(const void* p) {
    uint32_t a;
    asm("{ .reg .u64 t; cvta.to.shared.u64 t, %1; cvt.u32.u64 %0, t; }" : "=r"(a) : "l"(p));
    return a;
}

// ===========================================================================
// tf32 RN conversion pass
// ===========================================================================
__global__ void conv_tf32_kernel(const float4* __restrict__ in, uint4* __restrict__ out, int n4) {
    for (int i = blockIdx.x * blockDim.x + threadIdx.x; i < n4; i += gridDim.x * blockDim.x) {
        float4 v = in[i];
        uint4 o;
        asm("cvt.rna.tf32.f32 %0, %1;" : "=r"(o.x) : "f"(v.x));
        asm("cvt.rna.tf32.f32 %0, %1;" : "=r"(o.y) : "f"(v.y));
        asm("cvt.rna.tf32.f32 %0, %1;" : "=r"(o.z) : "f"(v.z));
        asm("cvt.rna.tf32.f32 %0, %1;" : "=r"(o.w) : "f"(v.w));
        out[i] = o;
    }
}

// Zero the per-row LN stats buffer
__global__ void zero_stats_kernel() {
    float4* p = (float4*)(g_scratch + OFF_STATS);
    p[blockIdx.x * 256 + threadIdx.x] = make_float4(0.f, 0.f, 0.f, 0.f);
}

// ===========================================================================
// tf32 mma.sync GEMM, tile 128(M) x 256(N) x 32(K), 512 threads,
// 16 warps (2m x 8n), warp tile 64x32, 4-stage cp.async ring, fused LN stats.
// ===========================================================================
#define STAGES 4
#define ITERS  32
#define STAGE_BYTES 49152     // A 16KB + B 32KB
#define ROW_BYTES 128

__device__ __forceinline__ void stage_load(uint32_t abase, uint32_t bbase,
                                           const float* __restrict__ A, const float* __restrict__ W,
                                           int m0, int n0, int kb, int tid) {
    // A: 1024 16B chunks (128 rows x 8), B: 2048 chunks (256 rows x 8)
    #pragma unroll
    for (int i = 0; i < 2; i++) {
        int c = tid + i * 512;
        int r = c >> 3, q = c & 7;
        uint32_t sw = (uint32_t)(r * ROW_BYTES + ((q ^ (r & 7)) << 4));
        const float* ga = A + (size_t)(m0 + r) * K_DIM + kb + q * 4;
        asm volatile("cp.async.cg.shared.global [%0], [%1], 16;" :: "r"(abase + sw), "l"(ga));
    }
    #pragma unroll
    for (int i = 0; i < 4; i++) {
        int c = tid + i * 512;
        int r = c >> 3, q = c & 7;
        uint32_t sw = (uint32_t)(r * ROW_BYTES + ((q ^ (r & 7)) << 4));
        const float* gb = W + (size_t)(n0 + r) * K_DIM + kb + q * 4;
        asm volatile("cp.async.cg.shared.global [%0], [%1], 16;" :: "r"(bbase + sw), "l"(gb));
    }
    asm volatile("cp.async.commit_group;" ::: "memory");
}

#define LDSM_X4(r0, r1, r2, r3, a) \
    asm volatile("ldmatrix.sync.aligned.m8n8.x4.shared.b16 {%0,%1,%2,%3}, [%4];" \
        : "=r"(r0), "=r"(r1), "=r"(r2), "=r"(r3) : "r"(a))

#define MMA_TF32(d, a, b) \
    asm volatile("mma.sync.aligned.m16n8k8.row.col.f32.tf32.tf32.f32 " \
        "{%0,%1,%2,%3}, {%4,%5,%6,%7}, {%8,%9}, {%0,%1,%2,%3};" \
        : "+f"((d)[0]), "+f"((d)[1]), "+f"((d)[2]), "+f"((d)[3]) \
        : "r"((a)[0]), "r"((a)[1]), "r"((a)[2]), "r"((a)[3]), "r"((b)[0]), "r"((b)[1]))

__global__ void __launch_bounds__(512, 1) gemm_tc_kernel(
    const float* __restrict__ A0, const float* __restrict__ A1,
    const float* __restrict__ W0, const float* __restrict__ W1)
{
    extern __shared__ __align__(128) char smem[];
    const uint32_t sb = smem_u32(smem);
    const int tid = threadIdx.x, wid = tid >> 5, l = tid & 31;
    const int m0 = blockIdx.y * 128, n0 = blockIdx.x * 256;
    const int z = blockIdx.z;
    const float* A = z ? A1 : A0;
    const float* W = z ? W1 : W0;
    float* C = g_scratch + (z ? OFF_H2H : OFF_I2H);
    float* stats = g_scratch + OFF_STATS + (size_t)z * B_ROWS * 2;

    const int mw = (wid & 1) * 64;       // 2 warps in m
    const int nw = (wid >> 1) * 32;      // 8 warps in n

    const int rA0 = mw + ((l >> 3) & 1) * 8 + (l & 7);
    const int cbA = (l >> 4);
    const int rB0 = nw + (l >> 4) * 8 + (l & 7);
    const int cbB = (l >> 3) & 1;

    uint32_t offA[4]; int xA[4];
    #pragma unroll
    for (int mf = 0; mf < 4; mf++) { int r = rA0 + mf * 16; offA[mf] = r * ROW_BYTES; xA[mf] = r & 7; }
    uint32_t offB[2]; int xB[2];
    #pragma unroll
    for (int p = 0; p < 2; p++) { int r = rB0 + p * 16; offB[p] = r * ROW_BYTES; xB[p] = r & 7; }

    float acc[4][4][4];
    #pragma unroll
    for (int mf = 0; mf < 4; mf++)
        #pragma unroll
        for (int nf = 0; nf < 4; nf++)
            #pragma unroll
            for (int e = 0; e < 4; e++) acc[mf][nf][e] = 0.f;

    #pragma unroll
    for (int s = 0; s < STAGES - 1; s++)
        stage_load(sb + s * STAGE_BYTES, sb + s * STAGE_BYTES + 16384, A, W, m0, n0, s * 32, tid);

    uint32_t af[2][4][4];
    uint32_t bf[2][2][4];

    for (int kt = 0; kt < ITERS; kt++) {
        asm volatile("cp.async.wait_group 2;" ::: "memory");
        __syncthreads();
        const uint32_t Ab = sb + (kt & (STAGES - 1)) * STAGE_BYTES;
        const uint32_t Bb = Ab + 16384;

        #pragma unroll
        for (int mf = 0; mf < 4; mf++) {
            uint32_t a = Ab + offA[mf] + ((cbA ^ xA[mf]) << 4);
            LDSM_X4(af[0][mf][0], af[0][mf][1], af[0][mf][2], af[0][mf][3], a);
        }
        #pragma unroll
        for (int p = 0; p < 2; p++) {
            uint32_t a = Bb + offB[p] + ((cbB ^ xB[p]) << 4);
            LDSM_X4(bf[0][p][0], bf[0][p][1], bf[0][p][2], bf[0][p][3], a);
        }

        if (kt + STAGES - 1 < ITERS) {
            const uint32_t Pb = sb + ((kt + STAGES - 1) & (STAGES - 1)) * STAGE_BYTES;
            stage_load(Pb, Pb + 16384, A, W, m0, n0, (kt + STAGES - 1) * 32, tid);
        } else {
            asm volatile("cp.async.commit_group;" ::: "memory");
        }

        #pragma unroll
        for (int j = 0; j < 4; j++) {
            const int cur = j & 1, nxt = cur ^ 1;
            if (j < 3) {
                const int q = 2 * (j + 1);
                #pragma unroll
                for (int mf = 0; mf < 4; mf++) {
                    uint32_t a = Ab + offA[mf] + (((q + cbA) ^ xA[mf]) << 4);
                    LDSM_X4(af[nxt][mf][0], af[nxt][mf][1], af[nxt][mf][2], af[nxt][mf][3], a);
                }
                #pragma unroll
                for (int p = 0; p < 2; p++) {
                    uint32_t a = Bb + offB[p] + (((q + cbB) ^ xB[p]) << 4);
                    LDSM_X4(bf[nxt][p][0], bf[nxt][p][1], bf[nxt][p][2], bf[nxt][p][3], a);
                }
            }
            #pragma unroll
            for (int mf = 0; mf < 4; mf++)
                #pragma unroll
                for (int nf = 0; nf < 4; nf++) {
                    uint32_t b2[2] = { bf[cur][nf >> 1][(nf & 1) * 2], bf[cur][nf >> 1][(nf & 1) * 2 + 1] };
                    MMA_TF32(acc[mf][nf], af[cur][mf], b2);
                }
        }
    }

    // ---- store C + fused per-row LN partial stats ----
    const int g = l >> 2, cc = (l & 3) * 2;
    #pragma unroll
    for (int mf = 0; mf < 4; mf++) {
        float s0 = 0.f, q0 = 0.f, s1 = 0.f, q1 = 0.f;
        #pragma unroll
        for (int nf = 0; nf < 4; nf++) {
            const int col = n0 + nw + nf * 8 + cc;
            float* p0 = C + (size_t)(m0 + mw + mf * 16 + g) * FH + col;
            float* p1 = p0 + 8 * FH;
            asm volatile("st.global.v2.f32 [%0], {%1,%2};" :: "l"(p0), "f"(acc[mf][nf][0]), "f"(acc[mf][nf][1]) : "memory");
            asm volatile("st.global.v2.f32 [%0], {%1,%2};" :: "l"(p1), "f"(acc[mf][nf][2]), "f"(acc[mf][nf][3]) : "memory");
            s0 += acc[mf][nf][0] + acc[mf][nf][1];
            q0 += acc[mf][nf][0] * acc[mf][nf][0] + acc[mf][nf][1] * acc[mf][nf][1];
            s1 += acc[mf][nf][2] + acc[mf][nf][3];
            q1 += acc[mf][nf][2] * acc[mf][nf][2] + acc[mf][nf][3] * acc[mf][nf][3];
        }
        #pragma unroll
        for (int o = 1; o < 4; o <<= 1) {
            s0 += __shfl_xor_sync(0xffffffffu, s0, o);
            q0 += __shfl_xor_sync(0xffffffffu, q0, o);
            s1 += __shfl_xor_sync(0xffffffffu, s1, o);
            q1 += __shfl_xor_sync(0xffffffffu, q1, o);
        }
        if ((l & 3) == 0) {
            const int r0 = m0 + mw + mf * 16 + g;
            atomicAdd(&stats[(size_t)r0 * 2 + 0], s0);
            atomicAdd(&stats[(size_t)r0 * 2 + 1], q0);
            atomicAdd(&stats[(size_t)(r0 + 8) * 2 + 0], s1);
            atomicAdd(&stats[(size_t)(r0 + 8) * 2 + 1], q1);
        }
    }
}

// ===========================================================================
// Streaming one-pass LN+LSTM epilogue (LN stats precomputed by GEMM)
// ===========================================================================
__device__ __forceinline__ float sigf(float x) { return 1.f / (1.f + expf(-x)); }

__global__ void __launch_bounds__(256, 4) epilogue_kernel(
    const float* __restrict__ c,
    const float* __restrict__ gi, const float* __restrict__ bi,
    const float* __restrict__ gh, const float* __restrict__ bh,
    const float* __restrict__ gc, const float* __restrict__ bc,
    const float* __restrict__ bias,
    float* __restrict__ out)
{
    __shared__ float red[16];
    const int row = blockIdx.x;
    const int t = threadIdx.x;

    const float2* sti_p = (const float2*)(g_scratch + OFF_STATS);
    const float2 sti = sti_p[row];
    const float2 sth = sti_p[B_ROWS + row];
    const float inv = 1.f / (float)FH;
    const float mu_i = sti.x * inv;
    const float mu_h = sth.x * inv;
    const float rs_i = rsqrtf(sti.y * inv - mu_i * mu_i + EPS);
    const float rs_h = rsqrtf(sth.y * inv - mu_h * mu_h + EPS);

    const float* i2h = g_scratch + OFF_I2H + (size_t)row * FH;
    const float* h2h = g_scratch + OFF_H2H + (size_t)row * FH;

    float4 lg4[4];
    #pragma unroll
    for (int gate = 0; gate < 4; gate++) {
        const int jo = gate * 1024 + 4 * t;
        const float4 vi = *(const float4*)(i2h + jo);
        const float4 vh = *(const float4*)(h2h + jo);
        const float4 ga = *(const float4*)(gi + jo);
        const float4 ba = *(const float4*)(bi + jo);
        const float4 gb = *(const float4*)(gh + jo);
        const float4 bb = *(const float4*)(bh + jo);
        const float4 bs = *(const float4*)(bias + jo);
        float4 r;
        r.x = (vi.x - mu_i) * rs_i * ga.x + ba.x + (vh.x - mu_h) * rs_h * gb.x + bb.x + bs.x;
        r.y = (vi.y - mu_i) * rs_i * ga.y + ba.y + (vh.y - mu_h) * rs_h * gb.y + bb.y + bs.y;
        r.z = (vi.z - mu_i) * rs_i * ga.z + ba.z + (vh.z - mu_h) * rs_h * gb.z + bb.z + bs.z;
        r.w = (vi.w - mu_i) * rs_i * ga.w + ba.w + (vh.w - mu_h) * rs_h * gb.w + bb.w + bs.w;
        lg4[gate] = r;
    }

    const float4 cv_old = *(const float4*)(c + (size_t)row * H_DIM + 4 * t);
    float4 cn;
    cn.x = sigf(lg4[0].x) * cv_old.x + sigf(lg4[1].x) * tanhf(lg4[3].x);
    cn.y = sigf(lg4[0].y) * cv_old.y + sigf(lg4[1].y) * tanhf(lg4[3].y);
    cn.z = sigf(lg4[0].z) * cv_old.z + sigf(lg4[1].z) * tanhf(lg4[3].z);
    cn.w = sigf(lg4[0].w) * cv_old.w + sigf(lg4[1].w) * tanhf(lg4[3].w);

    float cs1 = cn.x + cn.y + cn.z + cn.w;
    float cs2 = cn.x * cn.x + cn.y * cn.y + cn.z * cn.z + cn.w * cn.w;
    #pragma unroll
    for (int o = 16; o > 0; o >>= 1) {
        cs1 += __shfl_xor_sync(0xffffffffu, cs1, o);
        cs2 += __shfl_xor_sync(0xffffffffu, cs2, o);
    }
    if ((t & 31) == 0) { red[t >> 5] = cs1; red[8 + (t >> 5)] = cs2; }
    __syncthreads();
    float C1 = red[0], C2 = red[8];
    #pragma unroll
    for (int w = 1; w < 8; w++) { C1 += red[w]; C2 += red[8 + w]; }

    const float invH = 1.f / (float)H_DIM;
    const float mu_c = C1 * invH;
    const float rs_c = rsqrtf(C2 * invH - mu_c * mu_c + EPS);

    const float4 gcv = *(const float4*)(gc + 4 * t);
    const float4 bcv = *(const float4*)(bc + 4 * t);
    float4 hv;
    hv.x = sigf(lg4[2].x) * tanhf((cn.x - mu_c) * rs_c * gcv.x + bcv.x);
    hv.y = sigf(lg4[2].y) * tanhf((cn.y - mu_c) * rs_c * gcv.y + bcv.y);
    hv.z = sigf(lg4[2].z) * tanhf((cn.z - mu_c) * rs_c * gcv.z + bcv.z);
    hv.w = sigf(lg4[2].w) * tanhf((cn.w - mu_c) * rs_c * gcv.w + bcv.w);

    *(float4*)(out + (size_t)row * H_DIM + 4 * t) = hv;
    *(float4*)(out + (size_t)B_ROWS * H_DIM + (size_t)row * H_DIM + 4 * t) = cn;
}

// ===========================================================================
extern "C" void kernel_launch(void* const* d_in, const int* in_sizes, int n_in,
                              void* d_out, int out_size) {
    const float* x    = (const float*)d_in[0];
    const float* h    = (const float*)d_in[1];
    const float* c    = (const float*)d_in[2];
    const float* Wi   = (const float*)d_in[3];
    const float* Wh   = (const float*)d_in[4];
    const float* gi   = (const float*)d_in[5];
    const float* bi   = (const float*)d_in[6];
    const float* gh   = (const float*)d_in[7];
    const float* bh   = (const float*)d_in[8];
    const float* gc   = (const float*)d_in[9];
    const float* bc   = (const float*)d_in[10];
    const float* bias = (const float*)d_in[11];
    float* out = (float*)d_out;

    float* base = nullptr;
    cudaGetSymbolAddress((void**)&base, g_scratch);
    cudaFuncSetAttribute(gemm_tc_kernel, cudaFuncAttributeMaxDynamicSharedMemorySize,
                         STAGES * STAGE_BYTES);
    float* xc  = base + OFF_XC;
    float* hc  = base + OFF_HC;
    float* Wic = base + OFF_WIC;
    float* Whc = base + OFF_WHC;

    // 1) RN-convert operands to tf32
    conv_tf32_kernel<<<4096, 256>>>((const float4*)x,  (uint4*)xc,  (B_ROWS * K_DIM) / 4);
    conv_tf32_kernel<<<4096, 256>>>((const float4*)h,  (uint4*)hc,  (B_ROWS * H_DIM) / 4);
    conv_tf32_kernel<<<2048, 256>>>((const float4*)Wi, (uint4*)Wic, (FH * K_DIM) / 4);
    conv_tf32_kernel<<<2048, 256>>>((const float4*)Wh, (uint4*)Whc, (FH * H_DIM) / 4);

    // 2) zero LN stats
    zero_stats_kernel<<<64, 256>>>();

    // 3) tensor-core GEMMs + fused LN stats (tile 128x256, 512 threads)
    dim3 gg(FH / 256, B_ROWS / 128, 2);
    gemm_tc_kernel<<<gg, 512, STAGES * STAGE_BYTES>>>(xc, hc, Wic, Whc);

    // 4) streaming LN + LSTM epilogue
    epilogue_kernel<<<B_ROWS, 256>>>(c, gi, bi, gh, bh, gc, bc, bias, out);
}

// round 12
// speedup vs baseline: 1.3963x; 1.0719x over previous
#include <cuda_runtime.h>
#include <cuda_fp16.h>
#include <cstdint>
#include <math.h>

#define B_ROWS 16384
#define K_DIM  1024
#define H_DIM  1024
#define FH     4096
#define EPS    1e-5f

// Scratch (float units): [i2h+h2h as fp16: 2*16384*4096 halves = 64M floats]
// [xc 16M][hc 16M][Wic 4M][Whc 4M][stats 64K]
#define OFF_XC    67108864ull
#define OFF_HC    83886080ull
#define OFF_WIC   100663296ull
#define OFF_WHC   104857600ull
#define OFF_STATS 109051904ull
#define HOFF_H2H  67108864ull   // half units: h2h logits offset
__device__ float g_scratch[109117440];

__device__ __forceinline__ uint32_t smem_u32(const void* p) {
    uint32_t a;
    asm("{ .reg .u64 t; cvta.to.shared.u64 t, %1; cvt.u32.u64 %0, t; }" : "=r"(a) : "l"(p));
    return a;
}

// ===========================================================================
// tf32 RN conversion pass
// ===========================================================================
__global__ void conv_tf32_kernel(const float4* __restrict__ in, uint4* __restrict__ out, int n4) {
    for (int i = blockIdx.x * blockDim.x + threadIdx.x; i < n4; i += gridDim.x * blockDim.x) {
        float4 v = in[i];
        uint4 o;
        asm("cvt.rna.tf32.f32 %0, %1;" : "=r"(o.x) : "f"(v.x));
        asm("cvt.rna.tf32.f32 %0, %1;" : "=r"(o.y) : "f"(v.y));
        asm("cvt.rna.tf32.f32 %0, %1;" : "=r"(o.z) : "f"(v.z));
        asm("cvt.rna.tf32.f32 %0, %1;" : "=r"(o.w) : "f"(v.w));
        out[i] = o;
    }
}

// Zero the per-row LN stats buffer (65536 floats)
__global__ void zero_stats_kernel() {
    float4* p = (float4*)(g_scratch + OFF_STATS);
    p[blockIdx.x * 256 + threadIdx.x] = make_float4(0.f, 0.f, 0.f, 0.f);
}

// ===========================================================================
// tf32 mma.sync GEMM, tile 128(M) x 256(N) x 32(K), 256 threads,
// 8 warps (2m x 4n), warp tile 64x64, 4-stage cp.async ring,
// fused LN stats (fp32) + fp16 logit stores.
// ===========================================================================
#define STAGES 4
#define ITERS  32
#define STAGE_BYTES 49152     // A 16KB + B 32KB
#define ROW_BYTES 128

__device__ __forceinline__ void stage_load(uint32_t abase, uint32_t bbase,
                                           const float* __restrict__ A, const float* __restrict__ W,
                                           int m0, int n0, int kb, int tid) {
    #pragma unroll
    for (int i = 0; i < 4; i++) {
        int c = tid + i * 256;
        int r = c >> 3, q = c & 7;
        uint32_t sw = (uint32_t)(r * ROW_BYTES + ((q ^ (r & 7)) << 4));
        const float* ga = A + (size_t)(m0 + r) * K_DIM + kb + q * 4;
        asm volatile("cp.async.cg.shared.global [%0], [%1], 16;" :: "r"(abase + sw), "l"(ga));
    }
    #pragma unroll
    for (int i = 0; i < 8; i++) {
        int c = tid + i * 256;
        int r = c >> 3, q = c & 7;
        uint32_t sw = (uint32_t)(r * ROW_BYTES + ((q ^ (r & 7)) << 4));
        const float* gb = W + (size_t)(n0 + r) * K_DIM + kb + q * 4;
        asm volatile("cp.async.cg.shared.global [%0], [%1], 16;" :: "r"(bbase + sw), "l"(gb));
    }
    asm volatile("cp.async.commit_group;" ::: "memory");
}

#define LDSM_X4(r0, r1, r2, r3, a) \
    asm volatile("ldmatrix.sync.aligned.m8n8.x4.shared.b16 {%0,%1,%2,%3}, [%4];" \
        : "=r"(r0), "=r"(r1), "=r"(r2), "=r"(r3) : "r"(a))

#define MMA_TF32(d, a, b) \
    asm volatile("mma.sync.aligned.m16n8k8.row.col.f32.tf32.tf32.f32 " \
        "{%0,%1,%2,%3}, {%4,%5,%6,%7}, {%8,%9}, {%0,%1,%2,%3};" \
        : "+f"((d)[0]), "+f"((d)[1]), "+f"((d)[2]), "+f"((d)[3]) \
        : "r"((a)[0]), "r"((a)[1]), "r"((a)[2]), "r"((a)[3]), "r"((b)[0]), "r"((b)[1]))

__global__ void __launch_bounds__(256, 1) gemm_tc_kernel(
    const float* __restrict__ A0, const float* __restrict__ A1,
    const float* __restrict__ W0, const float* __restrict__ W1)
{
    extern __shared__ __align__(128) char smem[];
    const uint32_t sb = smem_u32(smem);
    const int tid = threadIdx.x, wid = tid >> 5, l = tid & 31;
    const int m0 = blockIdx.y * 128, n0 = blockIdx.x * 256;
    const int z = blockIdx.z;
    const float* A = z ? A1 : A0;
    const float* W = z ? W1 : W0;
    __half* C = reinterpret_cast<__half*>(g_scratch) + (z ? HOFF_H2H : 0);
    float* stats = g_scratch + OFF_STATS + (size_t)z * B_ROWS * 2;

    const int mw = (wid & 1) * 64;
    const int nw = (wid >> 1) * 64;

    const int rA0 = mw + ((l >> 3) & 1) * 8 + (l & 7);
    const int cbA = (l >> 4);
    const int rB0 = nw + (l >> 4) * 8 + (l & 7);
    const int cbB = (l >> 3) & 1;

    uint32_t offA[4]; int xA[4];
    #pragma unroll
    for (int mf = 0; mf < 4; mf++) { int r = rA0 + mf * 16; offA[mf] = r * ROW_BYTES; xA[mf] = r & 7; }
    uint32_t offB[4]; int xB[4];
    #pragma unroll
    for (int p = 0; p < 4; p++) { int r = rB0 + p * 16; offB[p] = r * ROW_BYTES; xB[p] = r & 7; }

    float acc[4][8][4];
    #pragma unroll
    for (int mf = 0; mf < 4; mf++)
        #pragma unroll
        for (int nf = 0; nf < 8; nf++)
            #pragma unroll
            for (int e = 0; e < 4; e++) acc[mf][nf][e] = 0.f;

    #pragma unroll
    for (int s = 0; s < STAGES - 1; s++)
        stage_load(sb + s * STAGE_BYTES, sb + s * STAGE_BYTES + 16384, A, W, m0, n0, s * 32, tid);

    uint32_t af[2][4][4];
    uint32_t bf[2][4][4];

    for (int kt = 0; kt < ITERS; kt++) {
        asm volatile("cp.async.wait_group 2;" ::: "memory");
        __syncthreads();
        const uint32_t Ab = sb + (kt & (STAGES - 1)) * STAGE_BYTES;
        const uint32_t Bb = Ab + 16384;

        #pragma unroll
        for (int mf = 0; mf < 4; mf++) {
            uint32_t a = Ab + offA[mf] + ((cbA ^ xA[mf]) << 4);
            LDSM_X4(af[0][mf][0], af[0][mf][1], af[0][mf][2], af[0][mf][3], a);
        }
        #pragma unroll
        for (int p = 0; p < 4; p++) {
            uint32_t a = Bb + offB[p] + ((cbB ^ xB[p]) << 4);
            LDSM_X4(bf[0][p][0], bf[0][p][1], bf[0][p][2], bf[0][p][3], a);
        }

        if (kt + STAGES - 1 < ITERS) {
            const uint32_t Pb = sb + ((kt + STAGES - 1) & (STAGES - 1)) * STAGE_BYTES;
            stage_load(Pb, Pb + 16384, A, W, m0, n0, (kt + STAGES - 1) * 32, tid);
        } else {
            asm volatile("cp.async.commit_group;" ::: "memory");
        }

        #pragma unroll
        for (int j = 0; j < 4; j++) {
            const int cur = j & 1, nxt = cur ^ 1;
            if (j < 3) {
                const int q = 2 * (j + 1);
                #pragma unroll
                for (int mf = 0; mf < 4; mf++) {
                    uint32_t a = Ab + offA[mf] + (((q + cbA) ^ xA[mf]) << 4);
                    LDSM_X4(af[nxt][mf][0], af[nxt][mf][1], af[nxt][mf][2], af[nxt][mf][3], a);
                }
                #pragma unroll
                for (int p = 0; p < 4; p++) {
                    uint32_t a = Bb + offB[p] + (((q + cbB) ^ xB[p]) << 4);
                    LDSM_X4(bf[nxt][p][0], bf[nxt][p][1], bf[nxt][p][2], bf[nxt][p][3], a);
                }
            }
            #pragma unroll
            for (int mf = 0; mf < 4; mf++)
                #pragma unroll
                for (int nf = 0; nf < 8; nf++) {
                    uint32_t b2[2] = { bf[cur][nf >> 1][(nf & 1) * 2], bf[cur][nf >> 1][(nf & 1) * 2 + 1] };
                    MMA_TF32(acc[mf][nf], af[cur][mf], b2);
                }
        }
    }

    // ---- store C (fp16) + fused per-row LN partial stats (fp32) ----
    const int g = l >> 2, cc = (l & 3) * 2;
    #pragma unroll
    for (int mf = 0; mf < 4; mf++) {
        float s0 = 0.f, q0 = 0.f, s1 = 0.f, q1 = 0.f;
        #pragma unroll
        for (int nf = 0; nf < 8; nf++) {
            const int col = n0 + nw + nf * 8 + cc;
            __half2* p0 = (__half2*)(C + (size_t)(m0 + mw + mf * 16 + g) * FH + col);
            __half2* p1 = (__half2*)((__half*)p0 + (size_t)8 * FH);
            *p0 = __floats2half2_rn(acc[mf][nf][0], acc[mf][nf][1]);
            *p1 = __floats2half2_rn(acc[mf][nf][2], acc[mf][nf][3]);
            s0 += acc[mf][nf][0] + acc[mf][nf][1];
            q0 += acc[mf][nf][0] * acc[mf][nf][0] + acc[mf][nf][1] * acc[mf][nf][1];
            s1 += acc[mf][nf][2] + acc[mf][nf][3];
            q1 += acc[mf][nf][2] * acc[mf][nf][2] + acc[mf][nf][3] * acc[mf][nf][3];
        }
        #pragma unroll
        for (int o = 1; o < 4; o <<= 1) {
            s0 += __shfl_xor_sync(0xffffffffu, s0, o);
            q0 += __shfl_xor_sync(0xffffffffu, q0, o);
            s1 += __shfl_xor_sync(0xffffffffu, s1, o);
            q1 += __shfl_xor_sync(0xffffffffu, q1, o);
        }
        if ((l & 3) == 0) {
            const int r0 = m0 + mw + mf * 16 + g;
            atomicAdd(&stats[(size_t)r0 * 2 + 0], s0);
            atomicAdd(&stats[(size_t)r0 * 2 + 1], q0);
            atomicAdd(&stats[(size_t)(r0 + 8) * 2 + 0], s1);
            atomicAdd(&stats[(size_t)(r0 + 8) * 2 + 1], q1);
        }
    }
}

// ===========================================================================
// Streaming one-pass LN+LSTM epilogue (fp16 logit reads, fp32 math)
// ===========================================================================
__device__ __forceinline__ float sigf(float x) { return 1.f / (1.f + expf(-x)); }

__global__ void __launch_bounds__(256, 4) epilogue_kernel(
    const float* __restrict__ c,
    const float* __restrict__ gi, const float* __restrict__ bi,
    const float* __restrict__ gh, const float* __restrict__ bh,
    const float* __restrict__ gc, const float* __restrict__ bc,
    const float* __restrict__ bias,
    float* __restrict__ out)
{
    __shared__ float red[16];
    const int row = blockIdx.x;
    const int t = threadIdx.x;

    const float2* sti_p = (const float2*)(g_scratch + OFF_STATS);
    const float2 sti = sti_p[row];
    const float2 sth = sti_p[B_ROWS + row];
    const float inv = 1.f / (float)FH;
    const float mu_i = sti.x * inv;
    const float mu_h = sth.x * inv;
    const float rs_i = rsqrtf(sti.y * inv - mu_i * mu_i + EPS);
    const float rs_h = rsqrtf(sth.y * inv - mu_h * mu_h + EPS);

    const __half* i2h = reinterpret_cast<const __half*>(g_scratch) + (size_t)row * FH;
    const __half* h2h = reinterpret_cast<const __half*>(g_scratch) + HOFF_H2H + (size_t)row * FH;

    float4 lg4[4];
    #pragma unroll
    for (int gate = 0; gate < 4; gate++) {
        const int jo = gate * 1024 + 4 * t;
        const uint2 ri = *(const uint2*)(i2h + jo);
        const uint2 rh = *(const uint2*)(h2h + jo);
        const float2 vi0 = __half22float2(*reinterpret_cast<const __half2*>(&ri.x));
        const float2 vi1 = __half22float2(*reinterpret_cast<const __half2*>(&ri.y));
        const float2 vh0 = __half22float2(*reinterpret_cast<const __half2*>(&rh.x));
        const float2 vh1 = __half22float2(*reinterpret_cast<const __half2*>(&rh.y));
        const float4 ga = *(const float4*)(gi + jo);
        const float4 ba = *(const float4*)(bi + jo);
        const float4 gb = *(const float4*)(gh + jo);
        const float4 bb = *(const float4*)(bh + jo);
        const float4 bs = *(const float4*)(bias + jo);
        float4 r;
        r.x = (vi0.x - mu_i) * rs_i * ga.x + ba.x + (vh0.x - mu_h) * rs_h * gb.x + bb.x + bs.x;
        r.y = (vi0.y - mu_i) * rs_i * ga.y + ba.y + (vh0.y - mu_h) * rs_h * gb.y + bb.y + bs.y;
        r.z = (vi1.x - mu_i) * rs_i * ga.z + ba.z + (vh1.x - mu_h) * rs_h * gb.z + bb.z + bs.z;
        r.w = (vi1.y - mu_i) * rs_i * ga.w + ba.w + (vh1.y - mu_h) * rs_h * gb.w + bb.w + bs.w;
        lg4[gate] = r;
    }

    const float4 cv_old = *(const float4*)(c + (size_t)row * H_DIM + 4 * t);
    float4 cn;
    cn.x = sigf(lg4[0].x) * cv_old.x + sigf(lg4[1].x) * tanhf(lg4[3].x);
    cn.y = sigf(lg4[0].y) * cv_old.y + sigf(lg4[1].y) * tanhf(lg4[3].y);
    cn.z = sigf(lg4[0].z) * cv_old.z + sigf(lg4[1].z) * tanhf(lg4[3].z);
    cn.w = sigf(lg4[0].w) * cv_old.w + sigf(lg4[1].w) * tanhf(lg4[3].w);

    float cs1 = cn.x + cn.y + cn.z + cn.w;
    float cs2 = cn.x * cn.x + cn.y * cn.y + cn.z * cn.z + cn.w * cn.w;
    #pragma unroll
    for (int o = 16; o > 0; o >>= 1) {
        cs1 += __shfl_xor_sync(0xffffffffu, cs1, o);
        cs2 += __shfl_xor_sync(0xffffffffu, cs2, o);
    }
    if ((t & 31) == 0) { red[t >> 5] = cs1; red[8 + (t >> 5)] = cs2; }
    __syncthreads();
    float C1 = red[0], C2 = red[8];
    #pragma unroll
    for (int w = 1; w < 8; w++) { C1 += red[w]; C2 += red[8 + w]; }

    const float invH = 1.f / (float)H_DIM;
    const float mu_c = C1 * invH;
    const float rs_c = rsqrtf(C2 * invH - mu_c * mu_c + EPS);

    const float4 gcv = *(const float4*)(gc + 4 * t);
    const float4 bcv = *(const float4*)(bc + 4 * t);
    float4 hv;
    hv.x = sigf(lg4[2].x) * tanhf((cn.x - mu_c) * rs_c * gcv.x + bcv.x);
    hv.y = sigf(lg4[2].y) * tanhf((cn.y - mu_c) * rs_c * gcv.y + bcv.y);
    hv.z = sigf(lg4[2].z) * tanhf((cn.z - mu_c) * rs_c * gcv.z + bcv.z);
    hv.w = sigf(lg4[2].w) * tanhf((cn.w - mu_c) * rs_c * gcv.w + bcv.w);

    *(float4*)(out + (size_t)row * H_DIM + 4 * t) = hv;
    *(float4*)(out + (size_t)B_ROWS * H_DIM + (size_t)row * H_DIM + 4 * t) = cn;
}

// ===========================================================================
extern "C" void kernel_launch(void* const* d_in, const int* in_sizes, int n_in,
                              void* d_out, int out_size) {
    const float* x    = (const float*)d_in[0];
    const float* h    = (const float*)d_in[1];
    const float* c    = (const float*)d_in[2];
    const float* Wi   = (const float*)d_in[3];
    const float* Wh   = (const float*)d_in[4];
    const float* gi   = (const float*)d_in[5];
    const float* bi   = (const float*)d_in[6];
    const float* gh   = (const float*)d_in[7];
    const float* bh   = (const float*)d_in[8];
    const float* gc   = (const float*)d_in[9];
    const float* bc   = (const float*)d_in[10];
    const float* bias = (const float*)d_in[11];
    float* out = (float*)d_out;

    float* base = nullptr;
    cudaGetSymbolAddress((void**)&base, g_scratch);
    cudaFuncSetAttribute(gemm_tc_kernel, cudaFuncAttributeMaxDynamicSharedMemorySize,
                         STAGES * STAGE_BYTES);
    float* xc  = base + OFF_XC;
    float* hc  = base + OFF_HC;
    float* Wic = base + OFF_WIC;
    float* Whc = base + OFF_WHC;

    // 1) zero LN stats (first, so ncu -s lands later on the GEMM)
    zero_stats_kernel<<<64, 256>>>();

    // 2) RN-convert operands to tf32
    conv_tf32_kernel<<<4096, 256>>>((const float4*)x,  (uint4*)xc,  (B_ROWS * K_DIM) / 4);
    conv_tf32_kernel<<<4096, 256>>>((const float4*)h,  (uint4*)hc,  (B_ROWS * H_DIM) / 4);
    conv_tf32_kernel<<<2048, 256>>>((const float4*)Wi, (uint4*)Wic, (FH * K_DIM) / 4);
    conv_tf32_kernel<<<2048, 256>>>((const float4*)Wh, (uint4*)Whc, (FH * H_DIM) / 4);

    // 3) tensor-core GEMMs + fused LN stats, fp16 logit stores
    dim3 gg(FH / 256, B_ROWS / 128, 2);
    gemm_tc_kernel<<<gg, 256, STAGES * STAGE_BYTES>>>(xc, hc, Wic, Whc);

    // 4) streaming LN + LSTM epilogue (fp16 logit reads)
    epilogue_kernel<<<B_ROWS, 256>>>(c, gi, bi, gh, bh, gc, bc, bias, out);
}

// round 14
// speedup vs baseline: 2.0957x; 1.5009x over previous
#include <cuda_runtime.h>
#include <cuda_fp16.h>
#include <cstdint>
#include <math.h>

#define B_ROWS 16384
#define K_DIM  1024
#define H_DIM  1024
#define FH     4096
#define EPS    1e-5f

// Scratch (float units): [logits fp16: 64M floats][xc 8M][hc 8M][Wic 2M][Whc 2M][stats 64K]
#define OFF_XC    67108864ull
#define OFF_HC    75497472ull
#define OFF_WIC   83886080ull
#define OFF_WHC   85983232ull
#define OFF_STATS 88080384ull
#define HOFF_H2H  67108864ull   // half units: h2h logits offset
__device__ float g_scratch[88145920];

__device__ __forceinline__ uint32_t smem_u32(const void* p) {
    uint32_t a;
    asm("{ .reg .u64 t; cvta.to.shared.u64 t, %1; cvt.u32.u64 %0, t; }" : "=r"(a) : "l"(p));
    return a;
}

// ===========================================================================
// fp32 -> fp16 RN conversion pass
// ===========================================================================
__global__ void conv_f16_kernel(const float4* __restrict__ in, uint2* __restrict__ out, int n4) {
    for (int i = blockIdx.x * blockDim.x + threadIdx.x; i < n4; i += gridDim.x * blockDim.x) {
        float4 v = in[i];
        __half2 h0 = __floats2half2_rn(v.x, v.y);
        __half2 h1 = __floats2half2_rn(v.z, v.w);
        uint2 o;
        o.x = *reinterpret_cast<uint32_t*>(&h0);
        o.y = *reinterpret_cast<uint32_t*>(&h1);
        out[i] = o;
    }
}

// Zero the per-row LN stats buffer (65536 floats)
__global__ void zero_stats_kernel() {
    float4* p = (float4*)(g_scratch + OFF_STATS);
    p[blockIdx.x * 256 + threadIdx.x] = make_float4(0.f, 0.f, 0.f, 0.f);
}

// ===========================================================================
// fp16 mma.sync GEMM (m16n8k16, fp32 accum), tile 128(M) x 256(N) x 64(K),
// 256 threads, 8 warps (2m x 4n), warp tile 64x64, 4-stage cp.async ring,
// fused LN stats (fp32) + fp16 logit stores.
// ===========================================================================
#define STAGES 4
#define ITERS  16             // K=1024 / BK=64
#define STAGE_BYTES 49152     // A 16KB + B 32KB (fp16, 128B rows = 64 halves)
#define ROW_BYTES 128

__device__ __forceinline__ void stage_load(uint32_t abase, uint32_t bbase,
                                           const __half* __restrict__ A, const __half* __restrict__ W,
                                           int m0, int n0, int kb, int tid) {
    // A: 1024 16B chunks (128 rows x 8), B: 2048 chunks (256 rows x 8); chunk = 8 halves
    #pragma unroll
    for (int i = 0; i < 4; i++) {
        int c = tid + i * 256;
        int r = c >> 3, q = c & 7;
        uint32_t sw = (uint32_t)(r * ROW_BYTES + ((q ^ (r & 7)) << 4));
        const __half* ga = A + (size_t)(m0 + r) * K_DIM + kb + q * 8;
        asm volatile("cp.async.cg.shared.global [%0], [%1], 16;" :: "r"(abase + sw), "l"(ga));
    }
    #pragma unroll
    for (int i = 0; i < 8; i++) {
        int c = tid + i * 256;
        int r = c >> 3, q = c & 7;
        uint32_t sw = (uint32_t)(r * ROW_BYTES + ((q ^ (r & 7)) << 4));
        const __half* gb = W + (size_t)(n0 + r) * K_DIM + kb + q * 8;
        asm volatile("cp.async.cg.shared.global [%0], [%1], 16;" :: "r"(bbase + sw), "l"(gb));
    }
    asm volatile("cp.async.commit_group;" ::: "memory");
}

#define LDSM_X4(r0, r1, r2, r3, a) \
    asm volatile("ldmatrix.sync.aligned.m8n8.x4.shared.b16 {%0,%1,%2,%3}, [%4];" \
        : "=r"(r0), "=r"(r1), "=r"(r2), "=r"(r3) : "r"(a))

#define MMA_F16(d, a, b0, b1) \
    asm volatile("mma.sync.aligned.m16n8k16.row.col.f32.f16.f16.f32 " \
        "{%0,%1,%2,%3}, {%4,%5,%6,%7}, {%8,%9}, {%0,%1,%2,%3};" \
        : "+f"((d)[0]), "+f"((d)[1]), "+f"((d)[2]), "+f"((d)[3]) \
        : "r"((a)[0]), "r"((a)[1]), "r"((a)[2]), "r"((a)[3]), "r"(b0), "r"(b1))

__global__ void __launch_bounds__(256, 1) gemm_tc_kernel(
    const __half* __restrict__ A0, const __half* __restrict__ A1,
    const __half* __restrict__ W0, const __half* __restrict__ W1)
{
    extern __shared__ __align__(128) char smem[];
    const uint32_t sb = smem_u32(smem);
    const int tid = threadIdx.x, wid = tid >> 5, l = tid & 31;
    const int m0 = blockIdx.y * 128, n0 = blockIdx.x * 256;
    const int z = blockIdx.z;
    const __half* A = z ? A1 : A0;
    const __half* W = z ? W1 : W0;
    __half* C = reinterpret_cast<__half*>(g_scratch) + (z ? HOFF_H2H : 0);
    float* stats = g_scratch + OFF_STATS + (size_t)z * B_ROWS * 2;

    const int mw = (wid & 1) * 64;
    const int nw = (wid >> 1) * 64;

    // ldmatrix lane mapping (matrices ordered [rows0-7,klo][rows8-15,klo][rows0-7,khi][rows8-15,khi])
    const int rA0 = mw + ((l >> 3) & 1) * 8 + (l & 7);
    const int cbA = (l >> 4);
    const int rB0 = nw + ((l >> 3) & 1) * 8 + (l & 7);
    const int cbB = (l >> 4);

    uint32_t offA[4]; int xA[4];
    #pragma unroll
    for (int mf = 0; mf < 4; mf++) { int r = rA0 + mf * 16; offA[mf] = r * ROW_BYTES; xA[mf] = r & 7; }
    uint32_t offB[4]; int xB[4];
    #pragma unroll
    for (int p = 0; p < 4; p++) { int r = rB0 + p * 16; offB[p] = r * ROW_BYTES; xB[p] = r & 7; }

    float acc[4][8][4];
    #pragma unroll
    for (int mf = 0; mf < 4; mf++)
        #pragma unroll
        for (int nf = 0; nf < 8; nf++)
            #pragma unroll
            for (int e = 0; e < 4; e++) acc[mf][nf][e] = 0.f;

    #pragma unroll
    for (int s = 0; s < STAGES - 1; s++)
        stage_load(sb + s * STAGE_BYTES, sb + s * STAGE_BYTES + 16384, A, W, m0, n0, s * 64, tid);

    uint32_t af[2][4][4];   // [buf][mf][a0..a3]
    uint32_t bf[2][4][4];   // [buf][pair][r0..r3]

    for (int kt = 0; kt < ITERS; kt++) {
        asm volatile("cp.async.wait_group 2;" ::: "memory");
        __syncthreads();
        const uint32_t Ab = sb + (kt & (STAGES - 1)) * STAGE_BYTES;
        const uint32_t Bb = Ab + 16384;

        // k-step 0 fragments (chunks cbA / cbB)
        #pragma unroll
        for (int mf = 0; mf < 4; mf++) {
            uint32_t a = Ab + offA[mf] + ((cbA ^ xA[mf]) << 4);
            LDSM_X4(af[0][mf][0], af[0][mf][1], af[0][mf][2], af[0][mf][3], a);
        }
        #pragma unroll
        for (int p = 0; p < 4; p++) {
            uint32_t a = Bb + offB[p] + ((cbB ^ xB[p]) << 4);
            LDSM_X4(bf[0][p][0], bf[0][p][1], bf[0][p][2], bf[0][p][3], a);
        }

        if (kt + STAGES - 1 < ITERS) {
            const uint32_t Pb = sb + ((kt + STAGES - 1) & (STAGES - 1)) * STAGE_BYTES;
            stage_load(Pb, Pb + 16384, A, W, m0, n0, (kt + STAGES - 1) * 64, tid);
        } else {
            asm volatile("cp.async.commit_group;" ::: "memory");
        }

        #pragma unroll
        for (int j = 0; j < 4; j++) {
            const int cur = j & 1, nxt = cur ^ 1;
            if (j < 3) {
                const int q = 2 * (j + 1);
                #pragma unroll
                for (int mf = 0; mf < 4; mf++) {
                    uint32_t a = Ab + offA[mf] + (((q + cbA) ^ xA[mf]) << 4);
                    LDSM_X4(af[nxt][mf][0], af[nxt][mf][1], af[nxt][mf][2], af[nxt][mf][3], a);
                }
                #pragma unroll
                for (int p = 0; p < 4; p++) {
                    uint32_t a = Bb + offB[p] + (((q + cbB) ^ xB[p]) << 4);
                    LDSM_X4(bf[nxt][p][0], bf[nxt][p][1], bf[nxt][p][2], bf[nxt][p][3], a);
                }
            }
            #pragma unroll
            for (int mf = 0; mf < 4; mf++)
                #pragma unroll
                for (int nf = 0; nf < 8; nf++) {
                    MMA_F16(acc[mf][nf], af[cur][mf],
                            bf[cur][nf >> 1][nf & 1], bf[cur][nf >> 1][(nf & 1) + 2]);
                }
        }
    }

    // ---- store C (fp16) + fused per-row LN partial stats (fp32) ----
    const int g = l >> 2, cc = (l & 3) * 2;
    #pragma unroll
    for (int mf = 0; mf < 4; mf++) {
        float s0 = 0.f, q0 = 0.f, s1 = 0.f, q1 = 0.f;
        #pragma unroll
        for (int nf = 0; nf < 8; nf++) {
            const int col = n0 + nw + nf * 8 + cc;
            __half2* p0 = (__half2*)(C + (size_t)(m0 + mw + mf * 16 + g) * FH + col);
            __half2* p1 = (__half2*)((__half*)p0 + (size_t)8 * FH);
            *p0 = __floats2half2_rn(acc[mf][nf][0], acc[mf][nf][1]);
            *p1 = __floats2half2_rn(acc[mf][nf][2], acc[mf][nf][3]);
            s0 += acc[mf][nf][0] + acc[mf][nf][1];
            q0 += acc[mf][nf][0] * acc[mf][nf][0] + acc[mf][nf][1] * acc[mf][nf][1];
            s1 += acc[mf][nf][2] + acc[mf][nf][3];
            q1 += acc[mf][nf][2] * acc[mf][nf][2] + acc[mf][nf][3] * acc[mf][nf][3];
        }
        #pragma unroll
        for (int o = 1; o < 4; o <<= 1) {
            s0 += __shfl_xor_sync(0xffffffffu, s0, o);
            q0 += __shfl_xor_sync(0xffffffffu, q0, o);
            s1 += __shfl_xor_sync(0xffffffffu, s1, o);
            q1 += __shfl_xor_sync(0xffffffffu, q1, o);
        }
        if ((l & 3) == 0) {
            const int r0 = m0 + mw + mf * 16 + g;
            atomicAdd(&stats[(size_t)r0 * 2 + 0], s0);
            atomicAdd(&stats[(size_t)r0 * 2 + 1], q0);
            atomicAdd(&stats[(size_t)(r0 + 8) * 2 + 0], s1);
            atomicAdd(&stats[(size_t)(r0 + 8) * 2 + 1], q1);
        }
    }
}

// ===========================================================================
// Streaming one-pass LN+LSTM epilogue (fp16 logit reads, fp32 math)
// ===========================================================================
__device__ __forceinline__ float sigf(float x) { return 1.f / (1.f + expf(-x)); }

__global__ void __launch_bounds__(256, 4) epilogue_kernel(
    const float* __restrict__ c,
    const float* __restrict__ gi, const float* __restrict__ bi,
    const float* __restrict__ gh, const float* __restrict__ bh,
    const float* __restrict__ gc, const float* __restrict__ bc,
    const float* __restrict__ bias,
    float* __restrict__ out)
{
    __shared__ float red[16];
    const int row = blockIdx.x;
    const int t = threadIdx.x;

    const float2* sti_p = (const float2*)(g_scratch + OFF_STATS);
    const float2 sti = sti_p[row];
    const float2 sth = sti_p[B_ROWS + row];
    const float inv = 1.f / (float)FH;
    const float mu_i = sti.x * inv;
    const float mu_h = sth.x * inv;
    const float rs_i = rsqrtf(sti.y * inv - mu_i * mu_i + EPS);
    const float rs_h = rsqrtf(sth.y * inv - mu_h * mu_h + EPS);

    const __half* i2h = reinterpret_cast<const __half*>(g_scratch) + (size_t)row * FH;
    const __half* h2h = reinterpret_cast<const __half*>(g_scratch) + HOFF_H2H + (size_t)row * FH;

    float4 lg4[4];
    #pragma unroll
    for (int gate = 0; gate < 4; gate++) {
        const int jo = gate * 1024 + 4 * t;
        const uint2 ri = *(const uint2*)(i2h + jo);
        const uint2 rh = *(const uint2*)(h2h + jo);
        const float2 vi0 = __half22float2(*reinterpret_cast<const __half2*>(&ri.x));
        const float2 vi1 = __half22float2(*reinterpret_cast<const __half2*>(&ri.y));
        const float2 vh0 = __half22float2(*reinterpret_cast<const __half2*>(&rh.x));
        const float2 vh1 = __half22float2(*reinterpret_cast<const __half2*>(&rh.y));
        const float4 ga = *(const float4*)(gi + jo);
        const float4 ba = *(const float4*)(bi + jo);
        const float4 gb = *(const float4*)(gh + jo);
        const float4 bb = *(const float4*)(bh + jo);
        const float4 bs = *(const float4*)(bias + jo);
        float4 r;
        r.x = (vi0.x - mu_i) * rs_i * ga.x + ba.x + (vh0.x - mu_h) * rs_h * gb.x + bb.x + bs.x;
        r.y = (vi0.y - mu_i) * rs_i * ga.y + ba.y + (vh0.y - mu_h) * rs_h * gb.y + bb.y + bs.y;
        r.z = (vi1.x - mu_i) * rs_i * ga.z + ba.z + (vh1.x - mu_h) * rs_h * gb.z + bb.z + bs.z;
        r.w = (vi1.y - mu_i) * rs_i * ga.w + ba.w + (vh1.y - mu_h) * rs_h * gb.w + bb.w + bs.w;
        lg4[gate] = r;
    }

    const float4 cv_old = *(const float4*)(c + (size_t)row * H_DIM + 4 * t);
    float4 cn;
    cn.x = sigf(lg4[0].x) * cv_old.x + sigf(lg4[1].x) * tanhf(lg4[3].x);
    cn.y = sigf(lg4[0].y) * cv_old.y + sigf(lg4[1].y) * tanhf(lg4[3].y);
    cn.z = sigf(lg4[0].z) * cv_old.z + sigf(lg4[1].z) * tanhf(lg4[3].z);
    cn.w = sigf(lg4[0].w) * cv_old.w + sigf(lg4[1].w) * tanhf(lg4[3].w);

    float cs1 = cn.x + cn.y + cn.z + cn.w;
    float cs2 = cn.x * cn.x + cn.y * cn.y + cn.z * cn.z + cn.w * cn.w;
    #pragma unroll
    for (int o = 16; o > 0; o >>= 1) {
        cs1 += __shfl_xor_sync(0xffffffffu, cs1, o);
        cs2 += __shfl_xor_sync(0xffffffffu, cs2, o);
    }
    if ((t & 31) == 0) { red[t >> 5] = cs1; red[8 + (t >> 5)] = cs2; }
    __syncthreads();
    float C1 = red[0], C2 = red[8];
    #pragma unroll
    for (int w = 1; w < 8; w++) { C1 += red[w]; C2 += red[8 + w]; }

    const float invH = 1.f / (float)H_DIM;
    const float mu_c = C1 * invH;
    const float rs_c = rsqrtf(C2 * invH - mu_c * mu_c + EPS);

    const float4 gcv = *(const float4*)(gc + 4 * t);
    const float4 bcv = *(const float4*)(bc + 4 * t);
    float4 hv;
    hv.x = sigf(lg4[2].x) * tanhf((cn.x - mu_c) * rs_c * gcv.x + bcv.x);
    hv.y = sigf(lg4[2].y) * tanhf((cn.y - mu_c) * rs_c * gcv.y + bcv.y);
    hv.z = sigf(lg4[2].z) * tanhf((cn.z - mu_c) * rs_c * gcv.z + bcv.z);
    hv.w = sigf(lg4[2].w) * tanhf((cn.w - mu_c) * rs_c * gcv.w + bcv.w);

    *(float4*)(out + (size_t)row * H_DIM + 4 * t) = hv;
    *(float4*)(out + (size_t)B_ROWS * H_DIM + (size_t)row * H_DIM + 4 * t) = cn;
}

// ===========================================================================
extern "C" void kernel_launch(void* const* d_in, const int* in_sizes, int n_in,
                              void* d_out, int out_size) {
    const float* x    = (const float*)d_in[0];
    const float* h    = (const float*)d_in[1];
    const float* c    = (const float*)d_in[2];
    const float* Wi   = (const float*)d_in[3];
    const float* Wh   = (const float*)d_in[4];
    const float* gi   = (const float*)d_in[5];
    const float* bi   = (const float*)d_in[6];
    const float* gh   = (const float*)d_in[7];
    const float* bh   = (const float*)d_in[8];
    const float* gc   = (const float*)d_in[9];
    const float* bc   = (const float*)d_in[10];
    const float* bias = (const float*)d_in[11];
    float* out = (float*)d_out;

    float* base = nullptr;
    cudaGetSymbolAddress((void**)&base, g_scratch);
    cudaFuncSetAttribute(gemm_tc_kernel, cudaFuncAttributeMaxDynamicSharedMemorySize,
                         STAGES * STAGE_BYTES);
    __half* xc  = (__half*)(base + OFF_XC);
    __half* hc  = (__half*)(base + OFF_HC);
    __half* Wic = (__half*)(base + OFF_WIC);
    __half* Whc = (__half*)(base + OFF_WHC);

    // 1) zero LN stats
    zero_stats_kernel<<<64, 256>>>();

    // 2) RN-convert operands to fp16
    conv_f16_kernel<<<4096, 256>>>((const float4*)x,  (uint2*)xc,  (B_ROWS * K_DIM) / 4);
    conv_f16_kernel<<<4096, 256>>>((const float4*)h,  (uint2*)hc,  (B_ROWS * H_DIM) / 4);
    conv_f16_kernel<<<2048, 256>>>((const float4*)Wi, (uint2*)Wic, (FH * K_DIM) / 4);
    conv_f16_kernel<<<2048, 256>>>((const float4*)Wh, (uint2*)Whc, (FH * H_DIM) / 4);

    // 3) fp16 tensor-core GEMMs + fused LN stats, fp16 logit stores
    dim3 gg(FH / 256, B_ROWS / 128, 2);
    gemm_tc_kernel<<<gg, 256, STAGES * STAGE_BYTES>>>(xc, hc, Wic, Whc);

    // 4) streaming LN + LSTM epilogue (fp16 logit reads)
    epilogue_kernel<<<B_ROWS, 256>>>(c, gi, bi, gh, bh, gc, bc, bias, out);
}

// round 15
// speedup vs baseline: 2.1419x; 1.0220x over previous
#include <cuda_runtime.h>
#include <cuda_fp16.h>
#include <cstdint>
#include <math.h>

#define B_ROWS 16384
#define K_DIM  1024
#define H_DIM  1024
#define FH     4096
#define EPS    1e-5f

// Scratch (float units): [logits fp16: 64M floats][xc 8M][hc 8M][Wic 2M][Whc 2M]
// [stats 64K][prep params ~16K]
#define OFF_XC    67108864ull
#define OFF_HC    75497472ull
#define OFF_WIC   83886080ull
#define OFF_WHC   85983232ull
#define OFF_STATS 88080384ull
#define OFF_P_GI  88145920ull   // 4096 halves (2048 floats)
#define OFF_P_GH  88147968ull   // 4096 halves
#define OFF_P_BS  88150016ull   // 4096 floats
#define OFF_P_GC  88154112ull   // 1024 halves (512 floats)
#define OFF_P_BC  88154624ull   // 1024 halves
#define HOFF_H2H  67108864ull   // half units: h2h logits offset
__device__ float g_scratch[88161280];

__device__ __forceinline__ uint32_t smem_u32(const void* p) {
    uint32_t a;
    asm("{ .reg .u64 t; cvta.to.shared.u64 t, %1; cvt.u32.u64 %0, t; }" : "=r"(a) : "l"(p));
    return a;
}

// ===========================================================================
// Fused fp32 -> fp16 RN conversion for x, h, Wi, Wh (outputs contiguous)
// ===========================================================================
#define N4_X  4194304   // 16M/4
#define N4_H  4194304
#define N4_WI 1048576
#define N4_WH 1048576
__global__ void conv_all_kernel(const float4* __restrict__ x, const float4* __restrict__ h,
                                const float4* __restrict__ Wi, const float4* __restrict__ Wh) {
    uint2* out = (uint2*)(g_scratch + OFF_XC);
    const int total = N4_X + N4_H + N4_WI + N4_WH;
    for (int i = blockIdx.x * blockDim.x + threadIdx.x; i < total; i += gridDim.x * blockDim.x) {
        float4 v;
        if (i < N4_X) v = x[i];
        else if (i < N4_X + N4_H) v = h[i - N4_X];
        else if (i < N4_X + N4_H + N4_WI) v = Wi[i - N4_X - N4_H];
        else v = Wh[i - N4_X - N4_H - N4_WI];
        __half2 h0 = __floats2half2_rn(v.x, v.y);
        __half2 h1 = __floats2half2_rn(v.z, v.w);
        uint2 o;
        o.x = *reinterpret_cast<uint32_t*>(&h0);
        o.y = *reinterpret_cast<uint32_t*>(&h1);
        out[i] = o;
    }
}

// Zero LN stats + precompute folded epilogue params
__global__ void prep_kernel(const float* __restrict__ gi, const float* __restrict__ bi,
                            const float* __restrict__ gh, const float* __restrict__ bh,
                            const float* __restrict__ gc, const float* __restrict__ bc,
                            const float* __restrict__ bias) {
    const int t = blockIdx.x * 256 + threadIdx.x;   // grid 128*256 = 32768
    if (t < 16384) {
        float4* p = (float4*)(g_scratch + OFF_STATS);
        p[t] = make_float4(0.f, 0.f, 0.f, 0.f);
    }
    if (t < FH) {
        ((__half*)(g_scratch + OFF_P_GI))[t] = __float2half_rn(gi[t]);
        ((__half*)(g_scratch + OFF_P_GH))[t] = __float2half_rn(gh[t]);
        (g_scratch + OFF_P_BS)[t] = bi[t] + bh[t] + bias[t];
    }
    if (t < H_DIM) {
        ((__half*)(g_scratch + OFF_P_GC))[t] = __float2half_rn(gc[t]);
        ((__half*)(g_scratch + OFF_P_BC))[t] = __float2half_rn(bc[t]);
    }
}

// ===========================================================================
// fp16 mma.sync GEMM (m16n8k16, fp32 accum), tile 128x256x64, 256 threads,
// 8 warps (2m x 4n), warp tile 64x64, 4-stage cp.async ring, fused LN stats.
// ===========================================================================
#define STAGES 4
#define ITERS  16
#define STAGE_BYTES 49152
#define ROW_BYTES 128

__device__ __forceinline__ void stage_load(uint32_t abase, uint32_t bbase,
                                           const __half* __restrict__ A, const __half* __restrict__ W,
                                           int m0, int n0, int kb, int tid) {
    #pragma unroll
    for (int i = 0; i < 4; i++) {
        int c = tid + i * 256;
        int r = c >> 3, q = c & 7;
        uint32_t sw = (uint32_t)(r * ROW_BYTES + ((q ^ (r & 7)) << 4));
        const __half* ga = A + (size_t)(m0 + r) * K_DIM + kb + q * 8;
        asm volatile("cp.async.cg.shared.global [%0], [%1], 16;" :: "r"(abase + sw), "l"(ga));
    }
    #pragma unroll
    for (int i = 0; i < 8; i++) {
        int c = tid + i * 256;
        int r = c >> 3, q = c & 7;
        uint32_t sw = (uint32_t)(r * ROW_BYTES + ((q ^ (r & 7)) << 4));
        const __half* gb = W + (size_t)(n0 + r) * K_DIM + kb + q * 8;
        asm volatile("cp.async.cg.shared.global [%0], [%1], 16;" :: "r"(bbase + sw), "l"(gb));
    }
    asm volatile("cp.async.commit_group;" ::: "memory");
}

#define LDSM_X4(r0, r1, r2, r3, a) \
    asm volatile("ldmatrix.sync.aligned.m8n8.x4.shared.b16 {%0,%1,%2,%3}, [%4];" \
        : "=r"(r0), "=r"(r1), "=r"(r2), "=r"(r3) : "r"(a))

#define MMA_F16(d, a, b0, b1) \
    asm volatile("mma.sync.aligned.m16n8k16.row.col.f32.f16.f16.f32 " \
        "{%0,%1,%2,%3}, {%4,%5,%6,%7}, {%8,%9}, {%0,%1,%2,%3};" \
        : "+f"((d)[0]), "+f"((d)[1]), "+f"((d)[2]), "+f"((d)[3]) \
        : "r"((a)[0]), "r"((a)[1]), "r"((a)[2]), "r"((a)[3]), "r"(b0), "r"(b1))

__global__ void __launch_bounds__(256, 1) gemm_tc_kernel(
    const __half* __restrict__ A0, const __half* __restrict__ A1,
    const __half* __restrict__ W0, const __half* __restrict__ W1)
{
    extern __shared__ __align__(128) char smem[];
    const uint32_t sb = smem_u32(smem);
    const int tid = threadIdx.x, wid = tid >> 5, l = tid & 31;
    const int m0 = blockIdx.y * 128, n0 = blockIdx.x * 256;
    const int z = blockIdx.z;
    const __half* A = z ? A1 : A0;
    const __half* W = z ? W1 : W0;
    __half* C = reinterpret_cast<__half*>(g_scratch) + (z ? HOFF_H2H : 0);
    float* stats = g_scratch + OFF_STATS + (size_t)z * B_ROWS * 2;

    const int mw = (wid & 1) * 64;
    const int nw = (wid >> 1) * 64;

    const int rA0 = mw + ((l >> 3) & 1) * 8 + (l & 7);
    const int cbA = (l >> 4);
    const int rB0 = nw + ((l >> 3) & 1) * 8 + (l & 7);
    const int cbB = (l >> 4);

    uint32_t offA[4]; int xA[4];
    #pragma unroll
    for (int mf = 0; mf < 4; mf++) { int r = rA0 + mf * 16; offA[mf] = r * ROW_BYTES; xA[mf] = r & 7; }
    uint32_t offB[4]; int xB[4];
    #pragma unroll
    for (int p = 0; p < 4; p++) { int r = rB0 + p * 16; offB[p] = r * ROW_BYTES; xB[p] = r & 7; }

    float acc[4][8][4];
    #pragma unroll
    for (int mf = 0; mf < 4; mf++)
        #pragma unroll
        for (int nf = 0; nf < 8; nf++)
            #pragma unroll
            for (int e = 0; e < 4; e++) acc[mf][nf][e] = 0.f;

    #pragma unroll
    for (int s = 0; s < STAGES - 1; s++)
        stage_load(sb + s * STAGE_BYTES, sb + s * STAGE_BYTES + 16384, A, W, m0, n0, s * 64, tid);

    uint32_t af[2][4][4];
    uint32_t bf[2][4][4];

    for (int kt = 0; kt < ITERS; kt++) {
        asm volatile("cp.async.wait_group 2;" ::: "memory");
        __syncthreads();
        const uint32_t Ab = sb + (kt & (STAGES - 1)) * STAGE_BYTES;
        const uint32_t Bb = Ab + 16384;

        #pragma unroll
        for (int mf = 0; mf < 4; mf++) {
            uint32_t a = Ab + offA[mf] + ((cbA ^ xA[mf]) << 4);
            LDSM_X4(af[0][mf][0], af[0][mf][1], af[0][mf][2], af[0][mf][3], a);
        }
        #pragma unroll
        for (int p = 0; p < 4; p++) {
            uint32_t a = Bb + offB[p] + ((cbB ^ xB[p]) << 4);
            LDSM_X4(bf[0][p][0], bf[0][p][1], bf[0][p][2], bf[0][p][3], a);
        }

        if (kt + STAGES - 1 < ITERS) {
            const uint32_t Pb = sb + ((kt + STAGES - 1) & (STAGES - 1)) * STAGE_BYTES;
            stage_load(Pb, Pb + 16384, A, W, m0, n0, (kt + STAGES - 1) * 64, tid);
        } else {
            asm volatile("cp.async.commit_group;" ::: "memory");
        }

        #pragma unroll
        for (int j = 0; j < 4; j++) {
            const int cur = j & 1, nxt = cur ^ 1;
            if (j < 3) {
                const int q = 2 * (j + 1);
                #pragma unroll
                for (int mf = 0; mf < 4; mf++) {
                    uint32_t a = Ab + offA[mf] + (((q + cbA) ^ xA[mf]) << 4);
                    LDSM_X4(af[nxt][mf][0], af[nxt][mf][1], af[nxt][mf][2], af[nxt][mf][3], a);
                }
                #pragma unroll
                for (int p = 0; p < 4; p++) {
                    uint32_t a = Bb + offB[p] + (((q + cbB) ^ xB[p]) << 4);
                    LDSM_X4(bf[nxt][p][0], bf[nxt][p][1], bf[nxt][p][2], bf[nxt][p][3], a);
                }
            }
            #pragma unroll
            for (int mf = 0; mf < 4; mf++)
                #pragma unroll
                for (int nf = 0; nf < 8; nf++) {
                    MMA_F16(acc[mf][nf], af[cur][mf],
                            bf[cur][nf >> 1][nf & 1], bf[cur][nf >> 1][(nf & 1) + 2]);
                }
        }
    }

    // ---- store C (fp16) + fused per-row LN partial stats (fp32) ----
    const int g = l >> 2, cc = (l & 3) * 2;
    #pragma unroll
    for (int mf = 0; mf < 4; mf++) {
        float s0 = 0.f, q0 = 0.f, s1 = 0.f, q1 = 0.f;
        #pragma unroll
        for (int nf = 0; nf < 8; nf++) {
            const int col = n0 + nw + nf * 8 + cc;
            __half2* p0 = (__half2*)(C + (size_t)(m0 + mw + mf * 16 + g) * FH + col);
            __half2* p1 = (__half2*)((__half*)p0 + (size_t)8 * FH);
            *p0 = __floats2half2_rn(acc[mf][nf][0], acc[mf][nf][1]);
            *p1 = __floats2half2_rn(acc[mf][nf][2], acc[mf][nf][3]);
            s0 += acc[mf][nf][0] + acc[mf][nf][1];
            q0 += acc[mf][nf][0] * acc[mf][nf][0] + acc[mf][nf][1] * acc[mf][nf][1];
            s1 += acc[mf][nf][2] + acc[mf][nf][3];
            q1 += acc[mf][nf][2] * acc[mf][nf][2] + acc[mf][nf][3] * acc[mf][nf][3];
        }
        #pragma unroll
        for (int o = 1; o < 4; o <<= 1) {
            s0 += __shfl_xor_sync(0xffffffffu, s0, o);
            q0 += __shfl_xor_sync(0xffffffffu, q0, o);
            s1 += __shfl_xor_sync(0xffffffffu, s1, o);
            q1 += __shfl_xor_sync(0xffffffffu, q1, o);
        }
        if ((l & 3) == 0) {
            const int r0 = m0 + mw + mf * 16 + g;
            atomicAdd(&stats[(size_t)r0 * 2 + 0], s0);
            atomicAdd(&stats[(size_t)r0 * 2 + 1], q0);
            atomicAdd(&stats[(size_t)(r0 + 8) * 2 + 0], s1);
            atomicAdd(&stats[(size_t)(r0 + 8) * 2 + 1], q1);
        }
    }
}

// ===========================================================================
// Streaming one-pass LN+LSTM epilogue: fp16 logits + folded fp16/fp32 params
// lf = (vi - mu_i)*rs_i*gi16 + (vh - mu_h)*rs_h*gh16 + Bs   (Bs = bi+bh+bias)
// ===========================================================================
__device__ __forceinline__ float sigf(float x) { return 1.f / (1.f + expf(-x)); }

__global__ void __launch_bounds__(256, 4) epilogue_kernel(
    const float* __restrict__ c, float* __restrict__ out)
{
    __shared__ float red[16];
    const int row = blockIdx.x;
    const int t = threadIdx.x;

    const float2* sti_p = (const float2*)(g_scratch + OFF_STATS);
    const float2 sti = sti_p[row];
    const float2 sth = sti_p[B_ROWS + row];
    const float inv = 1.f / (float)FH;
    const float mu_i = sti.x * inv;
    const float mu_h = sth.x * inv;
    const float rs_i = rsqrtf(sti.y * inv - mu_i * mu_i + EPS);
    const float rs_h = rsqrtf(sth.y * inv - mu_h * mu_h + EPS);

    const __half* i2h = reinterpret_cast<const __half*>(g_scratch) + (size_t)row * FH;
    const __half* h2h = reinterpret_cast<const __half*>(g_scratch) + HOFF_H2H + (size_t)row * FH;
    const __half* giP = (const __half*)(g_scratch + OFF_P_GI);
    const __half* ghP = (const __half*)(g_scratch + OFF_P_GH);
    const float*  bsP = g_scratch + OFF_P_BS;

    float4 lg4[4];
    #pragma unroll
    for (int gate = 0; gate < 4; gate++) {
        const int jo = gate * 1024 + 4 * t;
        const uint2 ri = *(const uint2*)(i2h + jo);
        const uint2 rh = *(const uint2*)(h2h + jo);
        const uint2 rg = *(const uint2*)(giP + jo);
        const uint2 rG = *(const uint2*)(ghP + jo);
        const float2 vi0 = __half22float2(*reinterpret_cast<const __half2*>(&ri.x));
        const float2 vi1 = __half22float2(*reinterpret_cast<const __half2*>(&ri.y));
        const float2 vh0 = __half22float2(*reinterpret_cast<const __half2*>(&rh.x));
        const float2 vh1 = __half22float2(*reinterpret_cast<const __half2*>(&rh.y));
        const float2 ga0 = __half22float2(*reinterpret_cast<const __half2*>(&rg.x));
        const float2 ga1 = __half22float2(*reinterpret_cast<const __half2*>(&rg.y));
        const float2 gb0 = __half22float2(*reinterpret_cast<const __half2*>(&rG.x));
        const float2 gb1 = __half22float2(*reinterpret_cast<const __half2*>(&rG.y));
        const float4 bs = *(const float4*)(bsP + jo);
        float4 r;
        r.x = (vi0.x - mu_i) * rs_i * ga0.x + (vh0.x - mu_h) * rs_h * gb0.x + bs.x;
        r.y = (vi0.y - mu_i) * rs_i * ga0.y + (vh0.y - mu_h) * rs_h * gb0.y + bs.y;
        r.z = (vi1.x - mu_i) * rs_i * ga1.x + (vh1.x - mu_h) * rs_h * gb1.x + bs.z;
        r.w = (vi1.y - mu_i) * rs_i * ga1.y + (vh1.y - mu_h) * rs_h * gb1.y + bs.w;
        lg4[gate] = r;
    }

    const float4 cv_old = *(const float4*)(c + (size_t)row * H_DIM + 4 * t);
    float4 cn;
    cn.x = sigf(lg4[0].x) * cv_old.x + sigf(lg4[1].x) * tanhf(lg4[3].x);
    cn.y = sigf(lg4[0].y) * cv_old.y + sigf(lg4[1].y) * tanhf(lg4[3].y);
    cn.z = sigf(lg4[0].z) * cv_old.z + sigf(lg4[1].z) * tanhf(lg4[3].z);
    cn.w = sigf(lg4[0].w) * cv_old.w + sigf(lg4[1].w) * tanhf(lg4[3].w);

    float cs1 = cn.x + cn.y + cn.z + cn.w;
    float cs2 = cn.x * cn.x + cn.y * cn.y + cn.z * cn.z + cn.w * cn.w;
    #pragma unroll
    for (int o = 16; o > 0; o >>= 1) {
        cs1 += __shfl_xor_sync(0xffffffffu, cs1, o);
        cs2 += __shfl_xor_sync(0xffffffffu, cs2, o);
    }
    if ((t & 31) == 0) { red[t >> 5] = cs1; red[8 + (t >> 5)] = cs2; }
    __syncthreads();
    float C1 = red[0], C2 = red[8];
    #pragma unroll
    for (int w = 1; w < 8; w++) { C1 += red[w]; C2 += red[8 + w]; }

    const float invH = 1.f / (float)H_DIM;
    const float mu_c = C1 * invH;
    const float rs_c = rsqrtf(C2 * invH - mu_c * mu_c + EPS);

    const uint2 rc = *(const uint2*)((const __half*)(g_scratch + OFF_P_GC) + 4 * t);
    const uint2 rb = *(const uint2*)((const __half*)(g_scratch + OFF_P_BC) + 4 * t);
    const float2 gc0 = __half22float2(*reinterpret_cast<const __half2*>(&rc.x));
    const float2 gc1 = __half22float2(*reinterpret_cast<const __half2*>(&rc.y));
    const float2 bc0 = __half22float2(*reinterpret_cast<const __half2*>(&rb.x));
    const float2 bc1 = __half22float2(*reinterpret_cast<const __half2*>(&rb.y));

    float4 hv;
    hv.x = sigf(lg4[2].x) * tanhf((cn.x - mu_c) * rs_c * gc0.x + bc0.x);
    hv.y = sigf(lg4[2].y) * tanhf((cn.y - mu_c) * rs_c * gc0.y + bc0.y);
    hv.z = sigf(lg4[2].z) * tanhf((cn.z - mu_c) * rs_c * gc1.x + bc1.x);
    hv.w = sigf(lg4[2].w) * tanhf((cn.w - mu_c) * rs_c * gc1.y + bc1.y);

    *(float4*)(out + (size_t)row * H_DIM + 4 * t) = hv;
    *(float4*)(out + (size_t)B_ROWS * H_DIM + (size_t)row * H_DIM + 4 * t) = cn;
}

// ===========================================================================
extern "C" void kernel_launch(void* const* d_in, const int* in_sizes, int n_in,
                              void* d_out, int out_size) {
    const float* x    = (const float*)d_in[0];
    const float* h    = (const float*)d_in[1];
    const float* c    = (const float*)d_in[2];
    const float* Wi   = (const float*)d_in[3];
    const float* Wh   = (const float*)d_in[4];
    const float* gi   = (const float*)d_in[5];
    const float* bi   = (const float*)d_in[6];
    const float* gh   = (const float*)d_in[7];
    const float* bh   = (const float*)d_in[8];
    const float* gc   = (const float*)d_in[9];
    const float* bc   = (const float*)d_in[10];
    const float* bias = (const float*)d_in[11];
    float* out = (float*)d_out;

    float* base = nullptr;
    cudaGetSymbolAddress((void**)&base, g_scratch);
    cudaFuncSetAttribute(gemm_tc_kernel, cudaFuncAttributeMaxDynamicSharedMemorySize,
                         STAGES * STAGE_BYTES);
    __half* xc  = (__half*)(base + OFF_XC);
    __half* hc  = (__half*)(base + OFF_HC);
    __half* Wic = (__half*)(base + OFF_WIC);
    __half* Whc = (__half*)(base + OFF_WHC);

    // 1) zero LN stats + fold epilogue params
    prep_kernel<<<128, 256>>>(gi, bi, gh, bh, gc, bc, bias);

    // 2) fused fp32 -> fp16 conversion of x, h, Wi, Wh
    conv_all_kernel<<<8192, 256>>>((const float4*)x, (const float4*)h,
                                   (const float4*)Wi, (const float4*)Wh);

    // 3) fp16 tensor-core GEMMs + fused LN stats, fp16 logit stores
    dim3 gg(FH / 256, B_ROWS / 128, 2);
    gemm_tc_kernel<<<gg, 256, STAGES * STAGE_BYTES>>>(xc, hc, Wic, Whc);

    // 4) streaming LN + LSTM epilogue (folded params)
    epilogue_kernel<<<B_ROWS, 256>>>(c, out);
}

// round 16
// speedup vs baseline: 2.1857x; 1.0205x over previous
#include <cuda_runtime.h>
#include <cuda_fp16.h>
#include <cstdint>
#include <math.h>

#define B_ROWS 16384
#define K_DIM  1024
#define H_DIM  1024
#define FH     4096
#define EPS    1e-5f

// Scratch (float units): [logits fp16: 64M floats][xc 8M][hc 8M][Wic 2M][Whc 2M]
// [stats 64K][prep params ~16K]
#define OFF_XC    67108864ull
#define OFF_HC    75497472ull
#define OFF_WIC   83886080ull
#define OFF_WHC   85983232ull
#define OFF_STATS 88080384ull
#define OFF_P_GI  88145920ull
#define OFF_P_GH  88147968ull
#define OFF_P_BS  88150016ull
#define OFF_P_GC  88154112ull
#define OFF_P_BC  88154624ull
#define HOFF_H2H  67108864ull
__device__ float g_scratch[88161280];

__device__ __forceinline__ uint32_t smem_u32(const void* p) {
    uint32_t a;
    asm("{ .reg .u64 t; cvta.to.shared.u64 t, %1; cvt.u32.u64 %0, t; }" : "=r"(a) : "l"(p));
    return a;
}

// ===========================================================================
// Fused fp32 -> fp16 RN conversion for x, h, Wi, Wh (outputs contiguous)
// ===========================================================================
#define N4_X  4194304
#define N4_H  4194304
#define N4_WI 1048576
#define N4_WH 1048576
__global__ void conv_all_kernel(const float4* __restrict__ x, const float4* __restrict__ h,
                                const float4* __restrict__ Wi, const float4* __restrict__ Wh) {
    uint2* out = (uint2*)(g_scratch + OFF_XC);
    const int total = N4_X + N4_H + N4_WI + N4_WH;
    for (int i = blockIdx.x * blockDim.x + threadIdx.x; i < total; i += gridDim.x * blockDim.x) {
        float4 v;
        if (i < N4_X) v = x[i];
        else if (i < N4_X + N4_H) v = h[i - N4_X];
        else if (i < N4_X + N4_H + N4_WI) v = Wi[i - N4_X - N4_H];
        else v = Wh[i - N4_X - N4_H - N4_WI];
        __half2 h0 = __floats2half2_rn(v.x, v.y);
        __half2 h1 = __floats2half2_rn(v.z, v.w);
        uint2 o;
        o.x = *reinterpret_cast<uint32_t*>(&h0);
        o.y = *reinterpret_cast<uint32_t*>(&h1);
        out[i] = o;
    }
}

// Zero LN stats + precompute folded epilogue params
__global__ void prep_kernel(const float* __restrict__ gi, const float* __restrict__ bi,
                            const float* __restrict__ gh, const float* __restrict__ bh,
                            const float* __restrict__ gc, const float* __restrict__ bc,
                            const float* __restrict__ bias) {
    const int t = blockIdx.x * 256 + threadIdx.x;
    if (t < 16384) {
        float4* p = (float4*)(g_scratch + OFF_STATS);
        p[t] = make_float4(0.f, 0.f, 0.f, 0.f);
    }
    if (t < FH) {
        ((__half*)(g_scratch + OFF_P_GI))[t] = __float2half_rn(gi[t]);
        ((__half*)(g_scratch + OFF_P_GH))[t] = __float2half_rn(gh[t]);
        (g_scratch + OFF_P_BS)[t] = bi[t] + bh[t] + bias[t];
    }
    if (t < H_DIM) {
        ((__half*)(g_scratch + OFF_P_GC))[t] = __float2half_rn(gc[t]);
        ((__half*)(g_scratch + OFF_P_BC))[t] = __float2half_rn(bc[t]);
    }
}

// ===========================================================================
// fp16 mma.sync GEMM (m16n8k16, fp32 accum), tile 128x256x64, 256 threads,
// 8 warps (2m x 4n), warp tile 64x64, 4-stage cp.async ring, fused LN stats.
// ===========================================================================
#define STAGES 4
#define ITERS  16
#define STAGE_BYTES 49152
#define ROW_BYTES 128

__device__ __forceinline__ void stage_load(uint32_t abase, uint32_t bbase,
                                           const __half* __restrict__ A, const __half* __restrict__ W,
                                           int m0, int n0, int kb, int tid) {
    #pragma unroll
    for (int i = 0; i < 4; i++) {
        int c = tid + i * 256;
        int r = c >> 3, q = c & 7;
        uint32_t sw = (uint32_t)(r * ROW_BYTES + ((q ^ (r & 7)) << 4));
        const __half* ga = A + (size_t)(m0 + r) * K_DIM + kb + q * 8;
        asm volatile("cp.async.cg.shared.global [%0], [%1], 16;" :: "r"(abase + sw), "l"(ga));
    }
    #pragma unroll
    for (int i = 0; i < 8; i++) {
        int c = tid + i * 256;
        int r = c >> 3, q = c & 7;
        uint32_t sw = (uint32_t)(r * ROW_BYTES + ((q ^ (r & 7)) << 4));
        const __half* gb = W + (size_t)(n0 + r) * K_DIM + kb + q * 8;
        asm volatile("cp.async.cg.shared.global [%0], [%1], 16;" :: "r"(bbase + sw), "l"(gb));
    }
    asm volatile("cp.async.commit_group;" ::: "memory");
}

#define LDSM_X4(r0, r1, r2, r3, a) \
    asm volatile("ldmatrix.sync.aligned.m8n8.x4.shared.b16 {%0,%1,%2,%3}, [%4];" \
        : "=r"(r0), "=r"(r1), "=r"(r2), "=r"(r3) : "r"(a))

#define MMA_F16(d, a, b0, b1) \
    asm volatile("mma.sync.aligned.m16n8k16.row.col.f32.f16.f16.f32 " \
        "{%0,%1,%2,%3}, {%4,%5,%6,%7}, {%8,%9}, {%0,%1,%2,%3};" \
        : "+f"((d)[0]), "+f"((d)[1]), "+f"((d)[2]), "+f"((d)[3]) \
        : "r"((a)[0]), "r"((a)[1]), "r"((a)[2]), "r"((a)[3]), "r"(b0), "r"(b1))

__global__ void __launch_bounds__(256, 1) gemm_tc_kernel(
    const __half* __restrict__ A0, const __half* __restrict__ A1,
    const __half* __restrict__ W0, const __half* __restrict__ W1)
{
    extern __shared__ __align__(128) char smem[];
    const uint32_t sb = smem_u32(smem);
    const int tid = threadIdx.x, wid = tid >> 5, l = tid & 31;
    const int m0 = blockIdx.y * 128, n0 = blockIdx.x * 256;
    const int z = blockIdx.z;
    const __half* A = z ? A1 : A0;
    const __half* W = z ? W1 : W0;
    __half* C = reinterpret_cast<__half*>(g_scratch) + (z ? HOFF_H2H : 0);
    float* stats = g_scratch + OFF_STATS + (size_t)z * B_ROWS * 2;

    const int mw = (wid & 1) * 64;
    const int nw = (wid >> 1) * 64;

    const int rA0 = mw + ((l >> 3) & 1) * 8 + (l & 7);
    const int cbA = (l >> 4);
    const int rB0 = nw + ((l >> 3) & 1) * 8 + (l & 7);
    const int cbB = (l >> 4);

    uint32_t offA[4]; int xA[4];
    #pragma unroll
    for (int mf = 0; mf < 4; mf++) { int r = rA0 + mf * 16; offA[mf] = r * ROW_BYTES; xA[mf] = r & 7; }
    uint32_t offB[4]; int xB[4];
    #pragma unroll
    for (int p = 0; p < 4; p++) { int r = rB0 + p * 16; offB[p] = r * ROW_BYTES; xB[p] = r & 7; }

    float acc[4][8][4];
    #pragma unroll
    for (int mf = 0; mf < 4; mf++)
        #pragma unroll
        for (int nf = 0; nf < 8; nf++)
            #pragma unroll
            for (int e = 0; e < 4; e++) acc[mf][nf][e] = 0.f;

    #pragma unroll
    for (int s = 0; s < STAGES - 1; s++)
        stage_load(sb + s * STAGE_BYTES, sb + s * STAGE_BYTES + 16384, A, W, m0, n0, s * 64, tid);

    uint32_t af[2][4][4];
    uint32_t bf[2][4][4];

    for (int kt = 0; kt < ITERS; kt++) {
        asm volatile("cp.async.wait_group 2;" ::: "memory");
        __syncthreads();
        const uint32_t Ab = sb + (kt & (STAGES - 1)) * STAGE_BYTES;
        const uint32_t Bb = Ab + 16384;

        #pragma unroll
        for (int mf = 0; mf < 4; mf++) {
            uint32_t a = Ab + offA[mf] + ((cbA ^ xA[mf]) << 4);
            LDSM_X4(af[0][mf][0], af[0][mf][1], af[0][mf][2], af[0][mf][3], a);
        }
        #pragma unroll
        for (int p = 0; p < 4; p++) {
            uint32_t a = Bb + offB[p] + ((cbB ^ xB[p]) << 4);
            LDSM_X4(bf[0][p][0], bf[0][p][1], bf[0][p][2], bf[0][p][3], a);
        }

        if (kt + STAGES - 1 < ITERS) {
            const uint32_t Pb = sb + ((kt + STAGES - 1) & (STAGES - 1)) * STAGE_BYTES;
            stage_load(Pb, Pb + 16384, A, W, m0, n0, (kt + STAGES - 1) * 64, tid);
        } else {
            asm volatile("cp.async.commit_group;" ::: "memory");
        }

        #pragma unroll
        for (int j = 0; j < 4; j++) {
            const int cur = j & 1, nxt = cur ^ 1;
            if (j < 3) {
                const int q = 2 * (j + 1);
                #pragma unroll
                for (int mf = 0; mf < 4; mf++) {
                    uint32_t a = Ab + offA[mf] + (((q + cbA) ^ xA[mf]) << 4);
                    LDSM_X4(af[nxt][mf][0], af[nxt][mf][1], af[nxt][mf][2], af[nxt][mf][3], a);
                }
                #pragma unroll
                for (int p = 0; p < 4; p++) {
                    uint32_t a = Bb + offB[p] + (((q + cbB) ^ xB[p]) << 4);
                    LDSM_X4(bf[nxt][p][0], bf[nxt][p][1], bf[nxt][p][2], bf[nxt][p][3], a);
                }
            }
            #pragma unroll
            for (int mf = 0; mf < 4; mf++)
                #pragma unroll
                for (int nf = 0; nf < 8; nf++) {
                    MMA_F16(acc[mf][nf], af[cur][mf],
                            bf[cur][nf >> 1][nf & 1], bf[cur][nf >> 1][(nf & 1) + 2]);
                }
        }
    }

    // ---- store C (fp16) + fused per-row LN partial stats (fp32) ----
    const int g = l >> 2, cc = (l & 3) * 2;
    #pragma unroll
    for (int mf = 0; mf < 4; mf++) {
        float s0 = 0.f, q0 = 0.f, s1 = 0.f, q1 = 0.f;
        #pragma unroll
        for (int nf = 0; nf < 8; nf++) {
            const int col = n0 + nw + nf * 8 + cc;
            __half2* p0 = (__half2*)(C + (size_t)(m0 + mw + mf * 16 + g) * FH + col);
            __half2* p1 = (__half2*)((__half*)p0 + (size_t)8 * FH);
            *p0 = __floats2half2_rn(acc[mf][nf][0], acc[mf][nf][1]);
            *p1 = __floats2half2_rn(acc[mf][nf][2], acc[mf][nf][3]);
            s0 += acc[mf][nf][0] + acc[mf][nf][1];
            q0 += acc[mf][nf][0] * acc[mf][nf][0] + acc[mf][nf][1] * acc[mf][nf][1];
            s1 += acc[mf][nf][2] + acc[mf][nf][3];
            q1 += acc[mf][nf][2] * acc[mf][nf][2] + acc[mf][nf][3] * acc[mf][nf][3];
        }
        #pragma unroll
        for (int o = 1; o < 4; o <<= 1) {
            s0 += __shfl_xor_sync(0xffffffffu, s0, o);
            q0 += __shfl_xor_sync(0xffffffffu, q0, o);
            s1 += __shfl_xor_sync(0xffffffffu, s1, o);
            q1 += __shfl_xor_sync(0xffffffffu, q1, o);
        }
        if ((l & 3) == 0) {
            const int r0 = m0 + mw + mf * 16 + g;
            atomicAdd(&stats[(size_t)r0 * 2 + 0], s0);
            atomicAdd(&stats[(size_t)r0 * 2 + 1], q0);
            atomicAdd(&stats[(size_t)(r0 + 8) * 2 + 0], s1);
            atomicAdd(&stats[(size_t)(r0 + 8) * 2 + 1], q1);
        }
    }
}

// ===========================================================================
// Streaming one-pass LN+LSTM epilogue: MUFU fast sigmoid/tanh
// ===========================================================================
__device__ __forceinline__ float fsig(float x) {
    return __fdividef(1.f, 1.f + __expf(-x));
}
__device__ __forceinline__ float ftanh(float x) {
    return __fdividef(2.f, 1.f + __expf(-2.f * x)) - 1.f;
}

__global__ void __launch_bounds__(256, 4) epilogue_kernel(
    const float* __restrict__ c, float* __restrict__ out)
{
    __shared__ float red[16];
    const int row = blockIdx.x;
    const int t = threadIdx.x;

    const float2* sti_p = (const float2*)(g_scratch + OFF_STATS);
    const float2 sti = sti_p[row];
    const float2 sth = sti_p[B_ROWS + row];
    const float inv = 1.f / (float)FH;
    const float mu_i = sti.x * inv;
    const float mu_h = sth.x * inv;
    const float rs_i = rsqrtf(sti.y * inv - mu_i * mu_i + EPS);
    const float rs_h = rsqrtf(sth.y * inv - mu_h * mu_h + EPS);

    const __half* i2h = reinterpret_cast<const __half*>(g_scratch) + (size_t)row * FH;
    const __half* h2h = reinterpret_cast<const __half*>(g_scratch) + HOFF_H2H + (size_t)row * FH;
    const __half* giP = (const __half*)(g_scratch + OFF_P_GI);
    const __half* ghP = (const __half*)(g_scratch + OFF_P_GH);
    const float*  bsP = g_scratch + OFF_P_BS;

    float4 lg4[4];
    #pragma unroll
    for (int gate = 0; gate < 4; gate++) {
        const int jo = gate * 1024 + 4 * t;
        const uint2 ri = *(const uint2*)(i2h + jo);
        const uint2 rh = *(const uint2*)(h2h + jo);
        const uint2 rg = *(const uint2*)(giP + jo);
        const uint2 rG = *(const uint2*)(ghP + jo);
        const float2 vi0 = __half22float2(*reinterpret_cast<const __half2*>(&ri.x));
        const float2 vi1 = __half22float2(*reinterpret_cast<const __half2*>(&ri.y));
        const float2 vh0 = __half22float2(*reinterpret_cast<const __half2*>(&rh.x));
        const float2 vh1 = __half22float2(*reinterpret_cast<const __half2*>(&rh.y));
        const float2 ga0 = __half22float2(*reinterpret_cast<const __half2*>(&rg.x));
        const float2 ga1 = __half22float2(*reinterpret_cast<const __half2*>(&rg.y));
        const float2 gb0 = __half22float2(*reinterpret_cast<const __half2*>(&rG.x));
        const float2 gb1 = __half22float2(*reinterpret_cast<const __half2*>(&rG.y));
        const float4 bs = *(const float4*)(bsP + jo);
        float4 r;
        r.x = (vi0.x - mu_i) * rs_i * ga0.x + (vh0.x - mu_h) * rs_h * gb0.x + bs.x;
        r.y = (vi0.y - mu_i) * rs_i * ga0.y + (vh0.y - mu_h) * rs_h * gb0.y + bs.y;
        r.z = (vi1.x - mu_i) * rs_i * ga1.x + (vh1.x - mu_h) * rs_h * gb1.x + bs.z;
        r.w = (vi1.y - mu_i) * rs_i * ga1.y + (vh1.y - mu_h) * rs_h * gb1.y + bs.w;
        lg4[gate] = r;
    }

    const float4 cv_old = *(const float4*)(c + (size_t)row * H_DIM + 4 * t);
    float4 cn;
    cn.x = fsig(lg4[0].x) * cv_old.x + fsig(lg4[1].x) * ftanh(lg4[3].x);
    cn.y = fsig(lg4[0].y) * cv_old.y + fsig(lg4[1].y) * ftanh(lg4[3].y);
    cn.z = fsig(lg4[0].z) * cv_old.z + fsig(lg4[1].z) * ftanh(lg4[3].z);
    cn.w = fsig(lg4[0].w) * cv_old.w + fsig(lg4[1].w) * ftanh(lg4[3].w);

    float cs1 = cn.x + cn.y + cn.z + cn.w;
    float cs2 = cn.x * cn.x + cn.y * cn.y + cn.z * cn.z + cn.w * cn.w;
    #pragma unroll
    for (int o = 16; o > 0; o >>= 1) {
        cs1 += __shfl_xor_sync(0xffffffffu, cs1, o);
        cs2 += __shfl_xor_sync(0xffffffffu, cs2, o);
    }
    if ((t & 31) == 0) { red[t >> 5] = cs1; red[8 + (t >> 5)] = cs2; }
    __syncthreads();
    float C1 = red[0], C2 = red[8];
    #pragma unroll
    for (int w = 1; w < 8; w++) { C1 += red[w]; C2 += red[8 + w]; }

    const float invH = 1.f / (float)H_DIM;
    const float mu_c = C1 * invH;
    const float rs_c = rsqrtf(C2 * invH - mu_c * mu_c + EPS);

    const uint2 rc = *(const uint2*)((const __half*)(g_scratch + OFF_P_GC) + 4 * t);
    const uint2 rb = *(const uint2*)((const __half*)(g_scratch + OFF_P_BC) + 4 * t);
    const float2 gc0 = __half22float2(*reinterpret_cast<const __half2*>(&rc.x));
    const float2 gc1 = __half22float2(*reinterpret_cast<const __half2*>(&rc.y));
    const float2 bc0 = __half22float2(*reinterpret_cast<const __half2*>(&rb.x));
    const float2 bc1 = __half22float2(*reinterpret_cast<const __half2*>(&rb.y));

    float4 hv;
    hv.x = fsig(lg4[2].x) * ftanh((cn.x - mu_c) * rs_c * gc0.x + bc0.x);
    hv.y = fsig(lg4[2].y) * ftanh((cn.y - mu_c) * rs_c * gc0.y + bc0.y);
    hv.z = fsig(lg4[2].z) * ftanh((cn.z - mu_c) * rs_c * gc1.x + bc1.x);
    hv.w = fsig(lg4[2].w) * ftanh((cn.w - mu_c) * rs_c * gc1.y + bc1.y);

    *(float4*)(out + (size_t)row * H_DIM + 4 * t) = hv;
    *(float4*)(out + (size_t)B_ROWS * H_DIM + (size_t)row * H_DIM + 4 * t) = cn;
}

// ===========================================================================
extern "C" void kernel_launch(void* const* d_in, const int* in_sizes, int n_in,
                              void* d_out, int out_size) {
    const float* x    = (const float*)d_in[0];
    const float* h    = (const float*)d_in[1];
    const float* c    = (const float*)d_in[2];
    const float* Wi   = (const float*)d_in[3];
    const float* Wh   = (const float*)d_in[4];
    const float* gi   = (const float*)d_in[5];
    const float* bi   = (const float*)d_in[6];
    const float* gh   = (const float*)d_in[7];
    const float* bh   = (const float*)d_in[8];
    const float* gc   = (const float*)d_in[9];
    const float* bc   = (const float*)d_in[10];
    const float* bias = (const float*)d_in[11];
    float* out = (float*)d_out;

    float* base = nullptr;
    cudaGetSymbolAddress((void**)&base, g_scratch);
    cudaFuncSetAttribute(gemm_tc_kernel, cudaFuncAttributeMaxDynamicSharedMemorySize,
                         STAGES * STAGE_BYTES);
    __half* xc  = (__half*)(base + OFF_XC);
    __half* hc  = (__half*)(base + OFF_HC);
    __half* Wic = (__half*)(base + OFF_WIC);
    __half* Whc = (__half*)(base + OFF_WHC);

    // 1) zero LN stats + fold epilogue params
    prep_kernel<<<128, 256>>>(gi, bi, gh, bh, gc, bc, bias);

    // 2) fused fp32 -> fp16 conversion of x, h, Wi, Wh
    conv_all_kernel<<<8192, 256>>>((const float4*)x, (const float4*)h,
                                   (const float4*)Wi, (const float4*)Wh);

    // 3) fp16 tensor-core GEMMs + fused LN stats, fp16 logit stores
    dim3 gg(FH / 256, B_ROWS / 128, 2);
    gemm_tc_kernel<<<gg, 256, STAGES * STAGE_BYTES>>>(xc, hc, Wic, Whc);

    // 4) streaming LN + LSTM epilogue (fast transcendentals)
    epilogue_kernel<<<B_ROWS, 256>>>(c, out);
}

// round 17
// speedup vs baseline: 2.2958x; 1.0503x over previous
#include <cuda_runtime.h>
#include <cuda_fp16.h>
#include <cstdint>
#include <math.h>

#define B_ROWS 16384
#define K_DIM  1024
#define H_DIM  1024
#define FH     4096
#define EPS    1e-5f

// Scratch (float units): [logits fp16: 64M floats][xc 8M][hc 8M][Wic 2M][Whc 2M]
// [stats 64K][prep params ~16K]
#define OFF_XC    67108864ull
#define OFF_HC    75497472ull
#define OFF_WIC   83886080ull
#define OFF_WHC   85983232ull
#define OFF_STATS 88080384ull
#define OFF_P_GI  88145920ull
#define OFF_P_GH  88147968ull
#define OFF_P_BS  88150016ull
#define OFF_P_GC  88154112ull
#define OFF_P_BC  88154624ull
#define HOFF_H2H  67108864ull
__device__ float g_scratch[88161280];

__device__ __forceinline__ uint32_t smem_u32(const void* p) {
    uint32_t a;
    asm("{ .reg .u64 t; cvta.to.shared.u64 t, %1; cvt.u32.u64 %0, t; }" : "=r"(a) : "l"(p));
    return a;
}

// ===========================================================================
// Fused fp32 -> fp16 RN conversion for x, h, Wi, Wh (outputs contiguous)
// ===========================================================================
#define N4_X  4194304
#define N4_H  4194304
#define N4_WI 1048576
#define N4_WH 1048576
__global__ void conv_all_kernel(const float4* __restrict__ x, const float4* __restrict__ h,
                                const float4* __restrict__ Wi, const float4* __restrict__ Wh) {
    uint2* out = (uint2*)(g_scratch + OFF_XC);
    const int total = N4_X + N4_H + N4_WI + N4_WH;
    for (int i = blockIdx.x * blockDim.x + threadIdx.x; i < total; i += gridDim.x * blockDim.x) {
        float4 v;
        if (i < N4_X) v = x[i];
        else if (i < N4_X + N4_H) v = h[i - N4_X];
        else if (i < N4_X + N4_H + N4_WI) v = Wi[i - N4_X - N4_H];
        else v = Wh[i - N4_X - N4_H - N4_WI];
        __half2 h0 = __floats2half2_rn(v.x, v.y);
        __half2 h1 = __floats2half2_rn(v.z, v.w);
        uint2 o;
        o.x = *reinterpret_cast<uint32_t*>(&h0);
        o.y = *reinterpret_cast<uint32_t*>(&h1);
        out[i] = o;
    }
}

// Zero LN stats + precompute folded epilogue params
__global__ void prep_kernel(const float* __restrict__ gi, const float* __restrict__ bi,
                            const float* __restrict__ gh, const float* __restrict__ bh,
                            const float* __restrict__ gc, const float* __restrict__ bc,
                            const float* __restrict__ bias) {
    const int t = blockIdx.x * 256 + threadIdx.x;
    if (t < 16384) {
        float4* p = (float4*)(g_scratch + OFF_STATS);
        p[t] = make_float4(0.f, 0.f, 0.f, 0.f);
    }
    if (t < FH) {
        ((__half*)(g_scratch + OFF_P_GI))[t] = __float2half_rn(gi[t]);
        ((__half*)(g_scratch + OFF_P_GH))[t] = __float2half_rn(gh[t]);
        (g_scratch + OFF_P_BS)[t] = bi[t] + bh[t] + bias[t];
    }
    if (t < H_DIM) {
        ((__half*)(g_scratch + OFF_P_GC))[t] = __float2half_rn(gc[t]);
        ((__half*)(g_scratch + OFF_P_BC))[t] = __float2half_rn(bc[t]);
    }
}

// ===========================================================================
// fp16 mma.sync GEMM (m16n8k16, fp32 accum), tile 128x256x64, 256 threads,
// 8 warps (2m x 4n), warp tile 64x64, 4-stage cp.async ring,
// prefetch issue SPREAD across k-steps, fused LN stats.
// ===========================================================================
#define STAGES 4
#define ITERS  16
#define STAGE_BYTES 49152
#define ROW_BYTES 128

// Chunked stage load: chunk 0 = A (rows 0-127), chunk 1 = B rows 0-127,
// chunk 2 = B rows 128-255. 4 cp.async per thread per chunk.
__device__ __forceinline__ void stage_load_chunk(uint32_t abase, uint32_t bbase,
                                                 const __half* __restrict__ A,
                                                 const __half* __restrict__ W,
                                                 int m0, int n0, int kb, int tid, int chunk) {
    if (chunk == 0) {
        #pragma unroll
        for (int i = 0; i < 4; i++) {
            int c = tid + i * 256;
            int r = c >> 3, q = c & 7;
            uint32_t sw = (uint32_t)(r * ROW_BYTES + ((q ^ (r & 7)) << 4));
            const __half* ga = A + (size_t)(m0 + r) * K_DIM + kb + q * 8;
            asm volatile("cp.async.cg.shared.global [%0], [%1], 16;" :: "r"(abase + sw), "l"(ga));
        }
    } else {
        const int base = (chunk - 1) * 1024;
        #pragma unroll
        for (int i = 0; i < 4; i++) {
            int c = tid + i * 256 + base;
            int r = c >> 3, q = c & 7;
            uint32_t sw = (uint32_t)(r * ROW_BYTES + ((q ^ (r & 7)) << 4));
            const __half* gb = W + (size_t)(n0 + r) * K_DIM + kb + q * 8;
            asm volatile("cp.async.cg.shared.global [%0], [%1], 16;" :: "r"(bbase + sw), "l"(gb));
        }
    }
}

#define LDSM_X4(r0, r1, r2, r3, a) \
    asm volatile("ldmatrix.sync.aligned.m8n8.x4.shared.b16 {%0,%1,%2,%3}, [%4];" \
        : "=r"(r0), "=r"(r1), "=r"(r2), "=r"(r3) : "r"(a))

#define MMA_F16(d, a, b0, b1) \
    asm volatile("mma.sync.aligned.m16n8k16.row.col.f32.f16.f16.f32 " \
        "{%0,%1,%2,%3}, {%4,%5,%6,%7}, {%8,%9}, {%0,%1,%2,%3};" \
        : "+f"((d)[0]), "+f"((d)[1]), "+f"((d)[2]), "+f"((d)[3]) \
        : "r"((a)[0]), "r"((a)[1]), "r"((a)[2]), "r"((a)[3]), "r"(b0), "r"(b1))

__global__ void __launch_bounds__(256, 1) gemm_tc_kernel(
    const __half* __restrict__ A0, const __half* __restrict__ A1,
    const __half* __restrict__ W0, const __half* __restrict__ W1)
{
    extern __shared__ __align__(128) char smem[];
    const uint32_t sb = smem_u32(smem);
    const int tid = threadIdx.x, wid = tid >> 5, l = tid & 31;
    const int m0 = blockIdx.y * 128, n0 = blockIdx.x * 256;
    const int z = blockIdx.z;
    const __half* A = z ? A1 : A0;
    const __half* W = z ? W1 : W0;
    __half* C = reinterpret_cast<__half*>(g_scratch) + (z ? HOFF_H2H : 0);
    float* stats = g_scratch + OFF_STATS + (size_t)z * B_ROWS * 2;

    const int mw = (wid & 1) * 64;
    const int nw = (wid >> 1) * 64;

    const int rA0 = mw + ((l >> 3) & 1) * 8 + (l & 7);
    const int cbA = (l >> 4);
    const int rB0 = nw + ((l >> 3) & 1) * 8 + (l & 7);
    const int cbB = (l >> 4);

    uint32_t offA[4]; int xA[4];
    #pragma unroll
    for (int mf = 0; mf < 4; mf++) { int r = rA0 + mf * 16; offA[mf] = r * ROW_BYTES; xA[mf] = r & 7; }
    uint32_t offB[4]; int xB[4];
    #pragma unroll
    for (int p = 0; p < 4; p++) { int r = rB0 + p * 16; offB[p] = r * ROW_BYTES; xB[p] = r & 7; }

    float acc[4][8][4];
    #pragma unroll
    for (int mf = 0; mf < 4; mf++)
        #pragma unroll
        for (int nf = 0; nf < 8; nf++)
            #pragma unroll
            for (int e = 0; e < 4; e++) acc[mf][nf][e] = 0.f;

    // prologue: fill STAGES-1 stages (burst is fine here — no MMA competition yet)
    #pragma unroll
    for (int s = 0; s < STAGES - 1; s++) {
        uint32_t ab = sb + s * STAGE_BYTES, bb = ab + 16384;
        #pragma unroll
        for (int ch = 0; ch < 3; ch++)
            stage_load_chunk(ab, bb, A, W, m0, n0, s * 64, tid, ch);
        asm volatile("cp.async.commit_group;" ::: "memory");
    }

    uint32_t af[2][4][4];
    uint32_t bf[2][4][4];

    for (int kt = 0; kt < ITERS; kt++) {
        asm volatile("cp.async.wait_group 2;" ::: "memory");
        __syncthreads();
        const uint32_t Ab = sb + (kt & (STAGES - 1)) * STAGE_BYTES;
        const uint32_t Bb = Ab + 16384;

        const bool pf = (kt + STAGES - 1 < ITERS);
        const uint32_t Pb = sb + ((kt + STAGES - 1) & (STAGES - 1)) * STAGE_BYTES;
        const int pkb = (kt + STAGES - 1) * 64;

        #pragma unroll
        for (int mf = 0; mf < 4; mf++) {
            uint32_t a = Ab + offA[mf] + ((cbA ^ xA[mf]) << 4);
            LDSM_X4(af[0][mf][0], af[0][mf][1], af[0][mf][2], af[0][mf][3], a);
        }
        #pragma unroll
        for (int p = 0; p < 4; p++) {
            uint32_t a = Bb + offB[p] + ((cbB ^ xB[p]) << 4);
            LDSM_X4(bf[0][p][0], bf[0][p][1], bf[0][p][2], bf[0][p][3], a);
        }

        #pragma unroll
        for (int j = 0; j < 4; j++) {
            const int cur = j & 1, nxt = cur ^ 1;
            if (j < 3) {
                const int q = 2 * (j + 1);
                #pragma unroll
                for (int mf = 0; mf < 4; mf++) {
                    uint32_t a = Ab + offA[mf] + (((q + cbA) ^ xA[mf]) << 4);
                    LDSM_X4(af[nxt][mf][0], af[nxt][mf][1], af[nxt][mf][2], af[nxt][mf][3], a);
                }
                #pragma unroll
                for (int p = 0; p < 4; p++) {
                    uint32_t a = Bb + offB[p] + (((q + cbB) ^ xB[p]) << 4);
                    LDSM_X4(bf[nxt][p][0], bf[nxt][p][1], bf[nxt][p][2], bf[nxt][p][3], a);
                }
                // spread prefetch: one chunk per k-step (j = 0,1,2)
                if (pf) stage_load_chunk(Pb, Pb + 16384, A, W, m0, n0, pkb, tid, j);
            } else {
                asm volatile("cp.async.commit_group;" ::: "memory");
            }
            #pragma unroll
            for (int mf = 0; mf < 4; mf++)
                #pragma unroll
                for (int nf = 0; nf < 8; nf++) {
                    MMA_F16(acc[mf][nf], af[cur][mf],
                            bf[cur][nf >> 1][nf & 1], bf[cur][nf >> 1][(nf & 1) + 2]);
                }
        }
    }

    // ---- store C (fp16) + fused per-row LN partial stats (fp32) ----
    const int g = l >> 2, cc = (l & 3) * 2;
    #pragma unroll
    for (int mf = 0; mf < 4; mf++) {
        float s0 = 0.f, q0 = 0.f, s1 = 0.f, q1 = 0.f;
        #pragma unroll
        for (int nf = 0; nf < 8; nf++) {
            const int col = n0 + nw + nf * 8 + cc;
            __half2* p0 = (__half2*)(C + (size_t)(m0 + mw + mf * 16 + g) * FH + col);
            __half2* p1 = (__half2*)((__half*)p0 + (size_t)8 * FH);
            *p0 = __floats2half2_rn(acc[mf][nf][0], acc[mf][nf][1]);
            *p1 = __floats2half2_rn(acc[mf][nf][2], acc[mf][nf][3]);
            s0 += acc[mf][nf][0] + acc[mf][nf][1];
            q0 += acc[mf][nf][0] * acc[mf][nf][0] + acc[mf][nf][1] * acc[mf][nf][1];
            s1 += acc[mf][nf][2] + acc[mf][nf][3];
            q1 += acc[mf][nf][2] * acc[mf][nf][2] + acc[mf][nf][3] * acc[mf][nf][3];
        }
        #pragma unroll
        for (int o = 1; o < 4; o <<= 1) {
            s0 += __shfl_xor_sync(0xffffffffu, s0, o);
            q0 += __shfl_xor_sync(0xffffffffu, q0, o);
            s1 += __shfl_xor_sync(0xffffffffu, s1, o);
            q1 += __shfl_xor_sync(0xffffffffu, q1, o);
        }
        if ((l & 3) == 0) {
            const int r0 = m0 + mw + mf * 16 + g;
            atomicAdd(&stats[(size_t)r0 * 2 + 0], s0);
            atomicAdd(&stats[(size_t)r0 * 2 + 1], q0);
            atomicAdd(&stats[(size_t)(r0 + 8) * 2 + 0], s1);
            atomicAdd(&stats[(size_t)(r0 + 8) * 2 + 1], q1);
        }
    }
}

// ===========================================================================
// Streaming one-pass LN+LSTM epilogue: MUFU fast sigmoid/tanh
// ===========================================================================
__device__ __forceinline__ float fsig(float x) {
    return __fdividef(1.f, 1.f + __expf(-x));
}
__device__ __forceinline__ float ftanh(float x) {
    return __fdividef(2.f, 1.f + __expf(-2.f * x)) - 1.f;
}

__global__ void __launch_bounds__(256, 4) epilogue_kernel(
    const float* __restrict__ c, float* __restrict__ out)
{
    __shared__ float red[16];
    const int row = blockIdx.x;
    const int t = threadIdx.x;

    const float2* sti_p = (const float2*)(g_scratch + OFF_STATS);
    const float2 sti = sti_p[row];
    const float2 sth = sti_p[B_ROWS + row];
    const float inv = 1.f / (float)FH;
    const float mu_i = sti.x * inv;
    const float mu_h = sth.x * inv;
    const float rs_i = rsqrtf(sti.y * inv - mu_i * mu_i + EPS);
    const float rs_h = rsqrtf(sth.y * inv - mu_h * mu_h + EPS);

    const __half* i2h = reinterpret_cast<const __half*>(g_scratch) + (size_t)row * FH;
    const __half* h2h = reinterpret_cast<const __half*>(g_scratch) + HOFF_H2H + (size_t)row * FH;
    const __half* giP = (const __half*)(g_scratch + OFF_P_GI);
    const __half* ghP = (const __half*)(g_scratch + OFF_P_GH);
    const float*  bsP = g_scratch + OFF_P_BS;

    float4 lg4[4];
    #pragma unroll
    for (int gate = 0; gate < 4; gate++) {
        const int jo = gate * 1024 + 4 * t;
        const uint2 ri = *(const uint2*)(i2h + jo);
        const uint2 rh = *(const uint2*)(h2h + jo);
        const uint2 rg = *(const uint2*)(giP + jo);
        const uint2 rG = *(const uint2*)(ghP + jo);
        const float2 vi0 = __half22float2(*reinterpret_cast<const __half2*>(&ri.x));
        const float2 vi1 = __half22float2(*reinterpret_cast<const __half2*>(&ri.y));
        const float2 vh0 = __half22float2(*reinterpret_cast<const __half2*>(&rh.x));
        const float2 vh1 = __half22float2(*reinterpret_cast<const __half2*>(&rh.y));
        const float2 ga0 = __half22float2(*reinterpret_cast<const __half2*>(&rg.x));
        const float2 ga1 = __half22float2(*reinterpret_cast<const __half2*>(&rg.y));
        const float2 gb0 = __half22float2(*reinterpret_cast<const __half2*>(&rG.x));
        const float2 gb1 = __half22float2(*reinterpret_cast<const __half2*>(&rG.y));
        const float4 bs = *(const float4*)(bsP + jo);
        float4 r;
        r.x = (vi0.x - mu_i) * rs_i * ga0.x + (vh0.x - mu_h) * rs_h * gb0.x + bs.x;
        r.y = (vi0.y - mu_i) * rs_i * ga0.y + (vh0.y - mu_h) * rs_h * gb0.y + bs.y;
        r.z = (vi1.x - mu_i) * rs_i * ga1.x + (vh1.x - mu_h) * rs_h * gb1.x + bs.z;
        r.w = (vi1.y - mu_i) * rs_i * ga1.y + (vh1.y - mu_h) * rs_h * gb1.y + bs.w;
        lg4[gate] = r;
    }

    const float4 cv_old = *(const float4*)(c + (size_t)row * H_DIM + 4 * t);
    float4 cn;
    cn.x = fsig(lg4[0].x) * cv_old.x + fsig(lg4[1].x) * ftanh(lg4[3].x);
    cn.y = fsig(lg4[0].y) * cv_old.y + fsig(lg4[1].y) * ftanh(lg4[3].y);
    cn.z = fsig(lg4[0].z) * cv_old.z + fsig(lg4[1].z) * ftanh(lg4[3].z);
    cn.w = fsig(lg4[0].w) * cv_old.w + fsig(lg4[1].w) * ftanh(lg4[3].w);

    float cs1 = cn.x + cn.y + cn.z + cn.w;
    float cs2 = cn.x * cn.x + cn.y * cn.y + cn.z * cn.z + cn.w * cn.w;
    #pragma unroll
    for (int o = 16; o > 0; o >>= 1) {
        cs1 += __shfl_xor_sync(0xffffffffu, cs1, o);
        cs2 += __shfl_xor_sync(0xffffffffu, cs2, o);
    }
    if ((t & 31) == 0) { red[t >> 5] = cs1; red[8 + (t >> 5)] = cs2; }
    __syncthreads();
    float C1 = red[0], C2 = red[8];
    #pragma unroll
    for (int w = 1; w < 8; w++) { C1 += red[w]; C2 += red[8 + w]; }

    const float invH = 1.f / (float)H_DIM;
    const float mu_c = C1 * invH;
    const float rs_c = rsqrtf(C2 * invH - mu_c * mu_c + EPS);

    const uint2 rc = *(const uint2*)((const __half*)(g_scratch + OFF_P_GC) + 4 * t);
    const uint2 rb = *(const uint2*)((const __half*)(g_scratch + OFF_P_BC) + 4 * t);
    const float2 gc0 = __half22float2(*reinterpret_cast<const __half2*>(&rc.x));
    const float2 gc1 = __half22float2(*reinterpret_cast<const __half2*>(&rc.y));
    const float2 bc0 = __half22float2(*reinterpret_cast<const __half2*>(&rb.x));
    const float2 bc1 = __half22float2(*reinterpret_cast<const __half2*>(&rb.y));

    float4 hv;
    hv.x = fsig(lg4[2].x) * ftanh((cn.x - mu_c) * rs_c * gc0.x + bc0.x);
    hv.y = fsig(lg4[2].y) * ftanh((cn.y - mu_c) * rs_c * gc0.y + bc0.y);
    hv.z = fsig(lg4[2].z) * ftanh((cn.z - mu_c) * rs_c * gc1.x + bc1.x);
    hv.w = fsig(lg4[2].w) * ftanh((cn.w - mu_c) * rs_c * gc1.y + bc1.y);

    *(float4*)(out + (size_t)row * H_DIM + 4 * t) = hv;
    *(float4*)(out + (size_t)B_ROWS * H_DIM + (size_t)row * H_DIM + 4 * t) = cn;
}

// ===========================================================================
extern "C" void kernel_launch(void* const* d_in, const int* in_sizes, int n_in,
                              void* d_out, int out_size) {
    const float* x    = (const float*)d_in[0];
    const float* h    = (const float*)d_in[1];
    const float* c    = (const float*)d_in[2];
    const float* Wi   = (const float*)d_in[3];
    const float* Wh   = (const float*)d_in[4];
    const float* gi   = (const float*)d_in[5];
    const float* bi   = (const float*)d_in[6];
    const float* gh   = (const float*)d_in[7];
    const float* bh   = (const float*)d_in[8];
    const float* gc   = (const float*)d_in[9];
    const float* bc   = (const float*)d_in[10];
    const float* bias = (const float*)d_in[11];
    float* out = (float*)d_out;

    float* base = nullptr;
    cudaGetSymbolAddress((void**)&base, g_scratch);
    cudaFuncSetAttribute(gemm_tc_kernel, cudaFuncAttributeMaxDynamicSharedMemorySize,
                         STAGES * STAGE_BYTES);
    __half* xc  = (__half*)(base + OFF_XC);
    __half* hc  = (__half*)(base + OFF_HC);
    __half* Wic = (__half*)(base + OFF_WIC);
    __half* Whc = (__half*)(base + OFF_WHC);

    // 1) zero LN stats + fold epilogue params
    prep_kernel<<<128, 256>>>(gi, bi, gh, bh, gc, bc, bias);

    // 2) fused fp32 -> fp16 conversion of x, h, Wi, Wh
    conv_all_kernel<<<8192, 256>>>((const float4*)x, (const float4*)h,
                                   (const float4*)Wi, (const float4*)Wh);

    // 3) fp16 tensor-core GEMMs + fused LN stats (spread prefetch issue)
    dim3 gg(FH / 256, B_ROWS / 128, 2);
    gemm_tc_kernel<<<gg, 256, STAGES * STAGE_BYTES>>>(xc, hc, Wic, Whc);

    // 4) streaming LN + LSTM epilogue (fast transcendentals)
    epilogue_kernel<<<B_ROWS, 256>>>(c, out);
}